// round 2
// baseline (speedup 1.0000x reference)
#include <cuda_runtime.h>

#define NN 50000
#define EE 800000
#define CIN 64
#define H1 4
#define C1 256   // H1*64
#define NEG 0.2f
#define NEGINF (-1e30f)

// ---------------- device scratch (no runtime allocation allowed) -----------
__device__ float g_h1[NN * C1];    // layer1 linear output  [N,4,64]
__device__ float g_h1r[NN * C1];   // relu(aggregated layer1) = layer2 input
__device__ float g_as1[NN * H1];
__device__ float g_ad1[NN * H1];
__device__ float g_h2[NN * CIN];   // layer2 linear output
__device__ float g_as2[NN];
__device__ float g_ad2[NN];
__device__ int   g_deg[NN];
__device__ int   g_offs[NN + 1];
__device__ int   g_cur[NN];
__device__ int   g_csrc[EE];       // CSR-by-dst: src node ids

__device__ __forceinline__ int clampN(int v) {
    return v < 0 ? 0 : (v >= NN ? NN - 1 : v);
}

// ---------------- CSR construction ----------------------------------------
__global__ void k_zero_deg() {
    int i = blockIdx.x * blockDim.x + threadIdx.x;
    if (i < NN) g_deg[i] = 0;
}

__global__ void k_count(const int* __restrict__ ei) {
    int e = blockIdx.x * blockDim.x + threadIdx.x;
    if (e < EE) atomicAdd(&g_deg[clampN(ei[EE + e])], 1);
}

// single-block exclusive scan over g_deg -> g_offs, g_cur
__global__ void k_scan() {
    __shared__ int sm[1024];
    __shared__ int carry;
    int t = threadIdx.x;
    if (t == 0) { carry = 0; g_offs[0] = 0; }
    __syncthreads();
    for (int base = 0; base < NN; base += 1024) {
        int i = base + t;
        int v = (i < NN) ? g_deg[i] : 0;
        sm[t] = v;
        __syncthreads();
        for (int off = 1; off < 1024; off <<= 1) {
            int u = (t >= off) ? sm[t - off] : 0;
            __syncthreads();
            sm[t] += u;
            __syncthreads();
        }
        int incl = sm[t] + carry;
        if (i < NN) {
            g_offs[i + 1] = incl;
            g_cur[i] = incl - v;   // exclusive prefix
        }
        __syncthreads();
        if (t == 1023) carry = incl;
        __syncthreads();
    }
}

__global__ void k_scatter(const int* __restrict__ ei) {
    int e = blockIdx.x * blockDim.x + threadIdx.x;
    if (e < EE) {
        int d = clampN(ei[EE + e]);
        int s = clampN(ei[e]);
        int p = atomicAdd(&g_cur[d], 1);
        g_csrc[p] = s;
    }
}

// ---------------- GEMM 1: h1 = x[N,64] @ W1[64,256] ------------------------
__global__ void __launch_bounds__(256) k_gemm1(const float* __restrict__ x,
                                               const float* __restrict__ W1) {
    __shared__ float sW[32 * C1];    // 32KB   (half of W1's K dim per phase)
    __shared__ float sx[32 * CIN];   // 8KB
    int t = threadIdx.x;
    int row0 = blockIdx.x * 32;
    for (int i = t; i < 32 * CIN; i += 256) {
        int r = i >> 6, c = i & 63;
        sx[i] = (row0 + r < NN) ? x[(row0 + r) * CIN + c] : 0.f;
    }
    float acc[32];
#pragma unroll
    for (int m = 0; m < 32; m++) acc[m] = 0.f;
    int c = t;
    for (int ph = 0; ph < 2; ph++) {
        __syncthreads();
        for (int i = t; i < 32 * C1; i += 256) sW[i] = W1[ph * 32 * C1 + i];
        __syncthreads();
#pragma unroll 4
        for (int k = 0; k < 32; k++) {
            float w = sW[k * C1 + c];
            int kk = ph * 32 + k;
#pragma unroll
            for (int m = 0; m < 32; m++) acc[m] += sx[m * CIN + kk] * w;
        }
    }
#pragma unroll
    for (int m = 0; m < 32; m++)
        if (row0 + m < NN) g_h1[(row0 + m) * C1 + c] = acc[m];
}

// ---------------- GEMM 2: h2 = h1r[N,256] @ W2[256,64] ---------------------
__global__ void __launch_bounds__(256) k_gemm2(const float* __restrict__ W2) {
    __shared__ float sW[32 * CIN];   // 8KB
    __shared__ float sx[32 * C1];    // 32KB
    int t = threadIdx.x;
    int row0 = blockIdx.x * 32;
    for (int i = t; i < 32 * C1; i += 256) {
        int r = i >> 8, c = i & 255;
        sx[i] = (row0 + r < NN) ? g_h1r[(row0 + r) * C1 + c] : 0.f;
    }
    int c = t & 63, rg = t >> 6;     // 4 row-groups of 8 rows
    float acc[8];
#pragma unroll
    for (int m = 0; m < 8; m++) acc[m] = 0.f;
    for (int ph = 0; ph < 8; ph++) {
        __syncthreads();
        for (int i = t; i < 32 * CIN; i += 256) sW[i] = W2[ph * 32 * CIN + i];
        __syncthreads();
#pragma unroll 4
        for (int k = 0; k < 32; k++) {
            float w = sW[k * CIN + c];
            int kk = ph * 32 + k;
#pragma unroll
            for (int m = 0; m < 8; m++)
                acc[m] += sx[(rg * 8 + m) * C1 + kk] * w;
        }
    }
#pragma unroll
    for (int m = 0; m < 8; m++) {
        int row = row0 + rg * 8 + m;
        if (row < NN) g_h2[row * CIN + c] = acc[m];
    }
}

// ---------------- attention scalar projections -----------------------------
// a_s[n,h] = sum_c h1[n,h*64+c] * att_src[h,c]   (flat index == column index)
__global__ void k_attn1(const float* __restrict__ asrc,
                        const float* __restrict__ adst) {
    int w = (blockIdx.x * blockDim.x + threadIdx.x) >> 5;
    int lane = threadIdx.x & 31;
    if (w >= NN) return;
    const float4* hp = (const float4*)(g_h1 + (size_t)w * C1);
    float v[8];
    *(float4*)(v)     = hp[2 * lane];
    *(float4*)(v + 4) = hp[2 * lane + 1];
    int cb = lane * 8;
    float ps = 0.f, pd = 0.f;
#pragma unroll
    for (int q = 0; q < 8; q++) {
        ps += v[q] * asrc[cb + q];
        pd += v[q] * adst[cb + q];
    }
    // reduce within 8-lane groups (one head per group)
#pragma unroll
    for (int off = 4; off; off >>= 1) {
        ps += __shfl_xor_sync(0xffffffffu, ps, off);
        pd += __shfl_xor_sync(0xffffffffu, pd, off);
    }
    if ((lane & 7) == 0) {
        int h = lane >> 3;
        g_as1[w * H1 + h] = ps;
        g_ad1[w * H1 + h] = pd;
    }
}

__global__ void k_attn2(const float* __restrict__ asrc,
                        const float* __restrict__ adst) {
    int w = (blockIdx.x * blockDim.x + threadIdx.x) >> 5;
    int lane = threadIdx.x & 31;
    if (w >= NN) return;
    const float2* hp = (const float2*)(g_h2 + (size_t)w * CIN);
    float2 v = hp[lane];
    int cb = lane * 2;
    float ps = v.x * asrc[cb] + v.y * asrc[cb + 1];
    float pd = v.x * adst[cb] + v.y * adst[cb + 1];
#pragma unroll
    for (int off = 16; off; off >>= 1) {
        ps += __shfl_xor_sync(0xffffffffu, ps, off);
        pd += __shfl_xor_sync(0xffffffffu, pd, off);
    }
    if (lane == 0) { g_as2[w] = ps; g_ad2[w] = pd; }
}

__device__ __forceinline__ float lrelu(float x) {
    return x > 0.f ? x : NEG * x;
}

// ---------------- layer-1 aggregation: warp per dst node -------------------
__global__ void __launch_bounds__(256) k_agg1(const float* __restrict__ b1) {
    int wid = (blockIdx.x * blockDim.x + threadIdx.x) >> 5;
    int lane = threadIdx.x & 31;
    if (wid >= NN) return;
    int beg = g_offs[wid], end = g_offs[wid + 1];
    int c0 = lane * 8;
    float* outp = g_h1r + (size_t)wid * C1 + c0;
    if (beg == end) {
        float4 o0, o1;
        o0.x = fmaxf(b1[c0 + 0], 0.f); o0.y = fmaxf(b1[c0 + 1], 0.f);
        o0.z = fmaxf(b1[c0 + 2], 0.f); o0.w = fmaxf(b1[c0 + 3], 0.f);
        o1.x = fmaxf(b1[c0 + 4], 0.f); o1.y = fmaxf(b1[c0 + 5], 0.f);
        o1.z = fmaxf(b1[c0 + 6], 0.f); o1.w = fmaxf(b1[c0 + 7], 0.f);
        *(float4*)(outp) = o0;
        *(float4*)(outp + 4) = o1;
        return;
    }
    float4 ad4 = *(const float4*)(g_ad1 + (size_t)wid * H1);
    float ad[4] = {ad4.x, ad4.y, ad4.z, ad4.w};
    float m[4], ds[4];
#pragma unroll
    for (int h = 0; h < 4; h++) { m[h] = NEGINF; ds[h] = 0.f; }
    // pass 1: per-lane online softmax stats over this dst's edges
    for (int i = beg + lane; i < end; i += 32) {
        int s = g_csrc[i];
        float4 as4 = *(const float4*)(g_as1 + (size_t)s * H1);
        float e[4] = {as4.x + ad[0], as4.y + ad[1], as4.z + ad[2], as4.w + ad[3]};
#pragma unroll
        for (int h = 0; h < 4; h++) {
            float ev = lrelu(e[h]);
            if (ev > m[h]) {
                ds[h] = ds[h] * __expf(m[h] - ev) + 1.f;
                m[h] = ev;
            } else {
                ds[h] += __expf(ev - m[h]);
            }
        }
    }
    // warp combine (m, d) per head
#pragma unroll
    for (int off = 16; off; off >>= 1) {
#pragma unroll
        for (int h = 0; h < 4; h++) {
            float mo = __shfl_xor_sync(0xffffffffu, m[h], off);
            float d_o = __shfl_xor_sync(0xffffffffu, ds[h], off);
            float M = fmaxf(m[h], mo);
            float nd = 0.f;
            if (ds[h] > 0.f) nd += ds[h] * __expf(m[h] - M);
            if (d_o > 0.f)  nd += d_o * __expf(mo - M);
            m[h] = M; ds[h] = nd;
        }
    }
    int head = lane >> 3;                 // 8 consecutive cols per lane
    float mh = m[head];
    float invh = 1.f / ds[head];
    float adh = ad[head];
    float acc[8];
#pragma unroll
    for (int q = 0; q < 8; q++) acc[q] = 0.f;
    // pass 2: weighted gather of h1[src]
    for (int i = beg; i < end; i++) {
        int s = g_csrc[i];
        float asv = g_as1[s * H1 + head];
        float e = lrelu(asv + adh);
        float wgt = __expf(e - mh) * invh;
        const float4* hp = (const float4*)(g_h1 + (size_t)s * C1 + c0);
        float4 a = hp[0], b = hp[1];
        acc[0] += wgt * a.x; acc[1] += wgt * a.y;
        acc[2] += wgt * a.z; acc[3] += wgt * a.w;
        acc[4] += wgt * b.x; acc[5] += wgt * b.y;
        acc[6] += wgt * b.z; acc[7] += wgt * b.w;
    }
    float4 o0, o1;
    o0.x = fmaxf(acc[0] + b1[c0 + 0], 0.f);
    o0.y = fmaxf(acc[1] + b1[c0 + 1], 0.f);
    o0.z = fmaxf(acc[2] + b1[c0 + 2], 0.f);
    o0.w = fmaxf(acc[3] + b1[c0 + 3], 0.f);
    o1.x = fmaxf(acc[4] + b1[c0 + 4], 0.f);
    o1.y = fmaxf(acc[5] + b1[c0 + 5], 0.f);
    o1.z = fmaxf(acc[6] + b1[c0 + 6], 0.f);
    o1.w = fmaxf(acc[7] + b1[c0 + 7], 0.f);
    *(float4*)(outp) = o0;
    *(float4*)(outp + 4) = o1;
}

// ---------------- layer-2 aggregation: warp per dst node -------------------
__global__ void __launch_bounds__(256) k_agg2(const float* __restrict__ b2,
                                              float* __restrict__ out) {
    int wid = (blockIdx.x * blockDim.x + threadIdx.x) >> 5;
    int lane = threadIdx.x & 31;
    if (wid >= NN) return;
    int beg = g_offs[wid], end = g_offs[wid + 1];
    int c0 = lane * 2;
    float* outp = out + (size_t)wid * CIN + c0;
    if (beg == end) {
        outp[0] = b2[c0];
        outp[1] = b2[c0 + 1];
        return;
    }
    float ad = g_ad2[wid];
    float m = NEGINF, ds = 0.f;
    for (int i = beg + lane; i < end; i += 32) {
        int s = g_csrc[i];
        float ev = lrelu(g_as2[s] + ad);
        if (ev > m) {
            ds = ds * __expf(m - ev) + 1.f;
            m = ev;
        } else {
            ds += __expf(ev - m);
        }
    }
#pragma unroll
    for (int off = 16; off; off >>= 1) {
        float mo = __shfl_xor_sync(0xffffffffu, m, off);
        float d_o = __shfl_xor_sync(0xffffffffu, ds, off);
        float M = fmaxf(m, mo);
        float nd = 0.f;
        if (ds > 0.f) nd += ds * __expf(m - M);
        if (d_o > 0.f) nd += d_o * __expf(mo - M);
        m = M; ds = nd;
    }
    float inv = 1.f / ds;
    float acc0 = 0.f, acc1 = 0.f;
    for (int i = beg; i < end; i++) {
        int s = g_csrc[i];
        float e = lrelu(g_as2[s] + ad);
        float wgt = __expf(e - m) * inv;
        float2 v = *(const float2*)(g_h2 + (size_t)s * CIN + c0);
        acc0 += wgt * v.x;
        acc1 += wgt * v.y;
    }
    outp[0] = acc0 + b2[c0];
    outp[1] = acc1 + b2[c0 + 1];
}

// ---------------- launcher -------------------------------------------------
extern "C" void kernel_launch(void* const* d_in, const int* in_sizes, int n_in,
                              void* d_out, int out_size) {
    const float* x    = (const float*)d_in[0];
    const int*   ei   = (const int*)d_in[1];   // int32: JAX x64 disabled downcasts int64
    const float* W1   = (const float*)d_in[2];
    const float* as1  = (const float*)d_in[3];
    const float* ad1  = (const float*)d_in[4];
    const float* b1   = (const float*)d_in[5];
    const float* W2   = (const float*)d_in[6];
    const float* as2  = (const float*)d_in[7];
    const float* ad2  = (const float*)d_in[8];
    const float* b2   = (const float*)d_in[9];
    float* out = (float*)d_out;

    k_zero_deg<<<(NN + 255) / 256, 256>>>();
    k_count<<<(EE + 255) / 256, 256>>>(ei);
    k_scan<<<1, 1024>>>();
    k_scatter<<<(EE + 255) / 256, 256>>>(ei);

    k_gemm1<<<(NN + 31) / 32, 256>>>(x, W1);
    k_attn1<<<(NN + 7) / 8, 256>>>(as1, ad1);
    k_agg1<<<(NN + 7) / 8, 256>>>(b1);

    k_gemm2<<<(NN + 31) / 32, 256>>>(W2);
    k_attn2<<<(NN + 7) / 8, 256>>>(as2, ad2);
    k_agg2<<<(NN + 7) / 8, 256>>>(b2, out);
}

// round 3
// speedup vs baseline: 1.4764x; 1.4764x over previous
#include <cuda_runtime.h>

#define NN 50000
#define EE 800000
#define CIN 64
#define H1 4
#define C1 256   // H1*64
#define NEG 0.2f
#define NEGINF (-1e30f)

// ---------------- device scratch (no runtime allocation allowed) -----------
__device__ float g_h1[NN * C1];    // layer1 linear output  [N,4,64]
__device__ float g_h1r[NN * C1];   // relu(aggregated layer1) = layer2 input
__device__ float g_as1[NN * H1];
__device__ float g_ad1[NN * H1];
__device__ float g_h2[NN * CIN];   // layer2 linear output
__device__ float g_as2[NN];
__device__ float g_ad2[NN];
__device__ int   g_deg[NN];
__device__ int   g_offs[NN + 1];
__device__ int   g_cur[NN];
__device__ int   g_csrc[EE];       // CSR-by-dst: src node ids
__device__ int   g_part[64];       // scan block partials

__device__ __forceinline__ int clampN(int v) {
    return v < 0 ? 0 : (v >= NN ? NN - 1 : v);
}

// ---------------- packed f32x2 helpers (Blackwell FFMA2) -------------------
__device__ __forceinline__ unsigned long long pk2(float x, float y) {
    unsigned long long r;
    asm("mov.b64 %0, {%1, %2};" : "=l"(r)
        : "r"(__float_as_uint(x)), "r"(__float_as_uint(y)));
    return r;
}
__device__ __forceinline__ void upk2(unsigned long long v, float &x, float &y) {
    unsigned int lo, hi;
    asm("mov.b64 {%0, %1}, %2;" : "=r"(lo), "=r"(hi) : "l"(v));
    x = __uint_as_float(lo); y = __uint_as_float(hi);
}
__device__ __forceinline__ void fma2(unsigned long long &d,
                                     unsigned long long a,
                                     unsigned long long b) {
    asm("fma.rn.f32x2 %0, %1, %2, %0;" : "+l"(d) : "l"(a), "l"(b));
}

// ---------------- CSR construction ----------------------------------------
__global__ void k_zero_deg() {
    int i = blockIdx.x * blockDim.x + threadIdx.x;
    if (i < NN) g_deg[i] = 0;
}

__global__ void k_count(const int* __restrict__ ei) {
    int e = blockIdx.x * blockDim.x + threadIdx.x;
    if (e < EE) atomicAdd(&g_deg[clampN(ei[EE + e])], 1);
}

// 3-stage scan: block-local inclusive -> partial scan -> add-back
__global__ void __launch_bounds__(1024) k_scan1() {
    __shared__ int wsum[32];
    int t = threadIdx.x, b = blockIdx.x;
    int i = b * 1024 + t;
    int lane = t & 31, w = t >> 5;
    int v = (i < NN) ? g_deg[i] : 0;
    int x = v;
#pragma unroll
    for (int off = 1; off < 32; off <<= 1) {
        int u = __shfl_up_sync(0xffffffffu, x, off);
        if (lane >= off) x += u;
    }
    if (lane == 31) wsum[w] = x;
    __syncthreads();
    if (w == 0) {
        int s = wsum[lane];
#pragma unroll
        for (int off = 1; off < 32; off <<= 1) {
            int u = __shfl_up_sync(0xffffffffu, s, off);
            if (lane >= off) s += u;
        }
        wsum[lane] = s;
    }
    __syncthreads();
    int incl = x + (w > 0 ? wsum[w - 1] : 0);
    if (i < NN) g_offs[i + 1] = incl;     // block-local inclusive
    if (t == 1023) g_part[b] = incl;
}

__global__ void k_scan2() {   // 1 block, 64 threads; 49 partials
    __shared__ int sm[64];
    int t = threadIdx.x;
    sm[t] = (t < 49) ? g_part[t] : 0;
    __syncthreads();
#pragma unroll
    for (int off = 1; off < 64; off <<= 1) {
        int u = (t >= off) ? sm[t - off] : 0;
        __syncthreads();
        sm[t] += u;
        __syncthreads();
    }
    if (t < 49) g_part[t] = t ? sm[t - 1] : 0;   // exclusive
}

__global__ void k_scan3() {
    int i = blockIdx.x * blockDim.x + threadIdx.x;
    if (i == 0) g_offs[0] = 0;
    if (i < NN) {
        int v = g_offs[i + 1] + g_part[i >> 10];
        g_offs[i + 1] = v;
        g_cur[i] = v - g_deg[i];
    }
}

__global__ void k_scatter(const int* __restrict__ ei) {
    int e = blockIdx.x * blockDim.x + threadIdx.x;
    if (e < EE) {
        int d = clampN(ei[EE + e]);
        int s = clampN(ei[e]);
        int p = atomicAdd(&g_cur[d], 1);
        g_csrc[p] = s;
    }
}

// ---------------- GEMM 1: h1 = x[N,64] @ W1[64,256] ------------------------
// Block: 64 rows x 256 cols; thread: 8 rows x 8 cols (4 f32x2 col-pairs).
__global__ void __launch_bounds__(256) k_gemm1(const float* __restrict__ x,
                                               const float* __restrict__ W1) {
    __shared__ float sx[64 * 32];    // [row][kchunk]  8KB
    __shared__ float sW[32 * 256];   // [k][col]      32KB
    int t = threadIdx.x;
    int row0 = blockIdx.x * 64;
    int cg = t & 31, rg = t >> 5;
    unsigned long long acc[8][4];
#pragma unroll
    for (int m = 0; m < 8; m++)
#pragma unroll
        for (int c = 0; c < 4; c++) acc[m][c] = 0ull;

    for (int kc = 0; kc < 2; kc++) {
        __syncthreads();
        {
            float4* s4 = (float4*)sx;
#pragma unroll
            for (int q = 0; q < 2; q++) {
                int idx = t + q * 256;           // 0..511
                int row = idx >> 3, j = idx & 7;
                float4 v = make_float4(0.f, 0.f, 0.f, 0.f);
                if (row0 + row < NN)
                    v = *(const float4*)(x + (size_t)(row0 + row) * 64 + kc * 32 + j * 4);
                s4[idx] = v;
            }
            float4* w4 = (float4*)sW;
            const float4* wg = (const float4*)(W1 + kc * 32 * 256);
#pragma unroll
            for (int q = 0; q < 8; q++) w4[t + q * 256] = wg[t + q * 256];
        }
        __syncthreads();
        const float* xrow = sx + rg * 8 * 32;
#pragma unroll 2
        for (int k4 = 0; k4 < 8; k4++) {
            float4 xq[8];
#pragma unroll
            for (int m = 0; m < 8; m++)
                xq[m] = *(const float4*)(xrow + m * 32 + k4 * 4);
#pragma unroll
            for (int j = 0; j < 4; j++) {
                const ulonglong2* wp =
                    (const ulonglong2*)(sW + (k4 * 4 + j) * 256 + cg * 8);
                ulonglong2 wa = wp[0];
                ulonglong2 wb = wp[1];
#pragma unroll
                for (int m = 0; m < 8; m++) {
                    float xs = (j == 0) ? xq[m].x : (j == 1) ? xq[m].y
                             : (j == 2) ? xq[m].z : xq[m].w;
                    unsigned long long xd = pk2(xs, xs);
                    fma2(acc[m][0], xd, wa.x);
                    fma2(acc[m][1], xd, wa.y);
                    fma2(acc[m][2], xd, wb.x);
                    fma2(acc[m][3], xd, wb.y);
                }
            }
        }
    }
#pragma unroll
    for (int m = 0; m < 8; m++) {
        int row = row0 + rg * 8 + m;
        if (row < NN) {
            float v[8];
            upk2(acc[m][0], v[0], v[1]);
            upk2(acc[m][1], v[2], v[3]);
            upk2(acc[m][2], v[4], v[5]);
            upk2(acc[m][3], v[6], v[7]);
            float* op = g_h1 + (size_t)row * C1 + cg * 8;
            *(float4*)op       = make_float4(v[0], v[1], v[2], v[3]);
            *(float4*)(op + 4) = make_float4(v[4], v[5], v[6], v[7]);
        }
    }
}

// ---------------- GEMM 2: h2 = h1r[N,256] @ W2[256,64] ---------------------
// Block: 128 rows x 64 cols; thread: 8 rows x 4 cols (2 f32x2 col-pairs).
__global__ void __launch_bounds__(256) k_gemm2(const float* __restrict__ W2) {
    __shared__ float sx[128 * 32];   // 16KB
    __shared__ float sW[32 * 64];    //  8KB
    int t = threadIdx.x;
    int row0 = blockIdx.x * 128;
    int cg = t & 15, rg = t >> 4;
    unsigned long long acc[8][2];
#pragma unroll
    for (int m = 0; m < 8; m++) { acc[m][0] = 0ull; acc[m][1] = 0ull; }

    for (int kc = 0; kc < 8; kc++) {
        __syncthreads();
        {
            float4* s4 = (float4*)sx;
#pragma unroll
            for (int q = 0; q < 4; q++) {
                int idx = t + q * 256;           // 0..1023
                int row = idx >> 3, j = idx & 7;
                float4 v = make_float4(0.f, 0.f, 0.f, 0.f);
                if (row0 + row < NN)
                    v = *(const float4*)(g_h1r + (size_t)(row0 + row) * C1 + kc * 32 + j * 4);
                s4[idx] = v;
            }
            float4* w4 = (float4*)sW;
            const float4* wg = (const float4*)(W2 + kc * 32 * 64);
#pragma unroll
            for (int q = 0; q < 2; q++) w4[t + q * 256] = wg[t + q * 256];
        }
        __syncthreads();
        const float* xrow = sx + rg * 8 * 32;
#pragma unroll 2
        for (int k4 = 0; k4 < 8; k4++) {
            float4 xq[8];
#pragma unroll
            for (int m = 0; m < 8; m++)
                xq[m] = *(const float4*)(xrow + m * 32 + k4 * 4);
#pragma unroll
            for (int j = 0; j < 4; j++) {
                ulonglong2 wv =
                    *(const ulonglong2*)(sW + (k4 * 4 + j) * 64 + cg * 4);
#pragma unroll
                for (int m = 0; m < 8; m++) {
                    float xs = (j == 0) ? xq[m].x : (j == 1) ? xq[m].y
                             : (j == 2) ? xq[m].z : xq[m].w;
                    unsigned long long xd = pk2(xs, xs);
                    fma2(acc[m][0], xd, wv.x);
                    fma2(acc[m][1], xd, wv.y);
                }
            }
        }
    }
#pragma unroll
    for (int m = 0; m < 8; m++) {
        int row = row0 + rg * 8 + m;
        if (row < NN) {
            float v[4];
            upk2(acc[m][0], v[0], v[1]);
            upk2(acc[m][1], v[2], v[3]);
            *(float4*)(g_h2 + (size_t)row * CIN + cg * 4) =
                make_float4(v[0], v[1], v[2], v[3]);
        }
    }
}

// ---------------- attention scalar projections -----------------------------
__global__ void k_attn1(const float* __restrict__ asrc,
                        const float* __restrict__ adst) {
    int w = (blockIdx.x * blockDim.x + threadIdx.x) >> 5;
    int lane = threadIdx.x & 31;
    if (w >= NN) return;
    const float4* hp = (const float4*)(g_h1 + (size_t)w * C1);
    float v[8];
    *(float4*)(v)     = hp[2 * lane];
    *(float4*)(v + 4) = hp[2 * lane + 1];
    int cb = lane * 8;
    float ps = 0.f, pd = 0.f;
#pragma unroll
    for (int q = 0; q < 8; q++) {
        ps += v[q] * asrc[cb + q];
        pd += v[q] * adst[cb + q];
    }
#pragma unroll
    for (int off = 4; off; off >>= 1) {
        ps += __shfl_xor_sync(0xffffffffu, ps, off);
        pd += __shfl_xor_sync(0xffffffffu, pd, off);
    }
    if ((lane & 7) == 0) {
        int h = lane >> 3;
        g_as1[w * H1 + h] = ps;
        g_ad1[w * H1 + h] = pd;
    }
}

__global__ void k_attn2(const float* __restrict__ asrc,
                        const float* __restrict__ adst) {
    int w = (blockIdx.x * blockDim.x + threadIdx.x) >> 5;
    int lane = threadIdx.x & 31;
    if (w >= NN) return;
    const float2* hp = (const float2*)(g_h2 + (size_t)w * CIN);
    float2 v = hp[lane];
    int cb = lane * 2;
    float ps = v.x * asrc[cb] + v.y * asrc[cb + 1];
    float pd = v.x * adst[cb] + v.y * adst[cb + 1];
#pragma unroll
    for (int off = 16; off; off >>= 1) {
        ps += __shfl_xor_sync(0xffffffffu, ps, off);
        pd += __shfl_xor_sync(0xffffffffu, pd, off);
    }
    if (lane == 0) { g_as2[w] = ps; g_ad2[w] = pd; }
}

__device__ __forceinline__ float lrelu(float x) {
    return x > 0.f ? x : NEG * x;
}

// ---------------- layer-1 aggregation: warp per dst node -------------------
__global__ void __launch_bounds__(256) k_agg1(const float* __restrict__ b1) {
    int wid = (blockIdx.x * blockDim.x + threadIdx.x) >> 5;
    int lane = threadIdx.x & 31;
    if (wid >= NN) return;
    int beg = g_offs[wid], end = g_offs[wid + 1];
    int c0 = lane * 8;
    float* outp = g_h1r + (size_t)wid * C1 + c0;
    if (beg == end) {
        float4 o0, o1;
        o0.x = fmaxf(b1[c0 + 0], 0.f); o0.y = fmaxf(b1[c0 + 1], 0.f);
        o0.z = fmaxf(b1[c0 + 2], 0.f); o0.w = fmaxf(b1[c0 + 3], 0.f);
        o1.x = fmaxf(b1[c0 + 4], 0.f); o1.y = fmaxf(b1[c0 + 5], 0.f);
        o1.z = fmaxf(b1[c0 + 6], 0.f); o1.w = fmaxf(b1[c0 + 7], 0.f);
        *(float4*)(outp) = o0;
        *(float4*)(outp + 4) = o1;
        return;
    }
    float4 ad4 = *(const float4*)(g_ad1 + (size_t)wid * H1);
    float ad[4] = {ad4.x, ad4.y, ad4.z, ad4.w};
    float m[4], ds[4];
#pragma unroll
    for (int h = 0; h < 4; h++) { m[h] = NEGINF; ds[h] = 0.f; }
    for (int i = beg + lane; i < end; i += 32) {
        int s = g_csrc[i];
        float4 as4 = *(const float4*)(g_as1 + (size_t)s * H1);
        float e[4] = {as4.x + ad[0], as4.y + ad[1], as4.z + ad[2], as4.w + ad[3]};
#pragma unroll
        for (int h = 0; h < 4; h++) {
            float ev = lrelu(e[h]);
            if (ev > m[h]) {
                ds[h] = ds[h] * __expf(m[h] - ev) + 1.f;
                m[h] = ev;
            } else {
                ds[h] += __expf(ev - m[h]);
            }
        }
    }
#pragma unroll
    for (int off = 16; off; off >>= 1) {
#pragma unroll
        for (int h = 0; h < 4; h++) {
            float mo = __shfl_xor_sync(0xffffffffu, m[h], off);
            float d_o = __shfl_xor_sync(0xffffffffu, ds[h], off);
            float M = fmaxf(m[h], mo);
            float nd = 0.f;
            if (ds[h] > 0.f) nd += ds[h] * __expf(m[h] - M);
            if (d_o > 0.f)  nd += d_o * __expf(mo - M);
            m[h] = M; ds[h] = nd;
        }
    }
    int head = lane >> 3;
    float mh = m[head];
    float invh = 1.f / ds[head];
    float adh = ad[head];
    float acc[8];
#pragma unroll
    for (int q = 0; q < 8; q++) acc[q] = 0.f;
    int i = beg;
    // 4-way unrolled gather for MLP
    for (; i + 4 <= end; i += 4) {
        int s0 = g_csrc[i], s1 = g_csrc[i + 1], s2 = g_csrc[i + 2], s3 = g_csrc[i + 3];
        float A0 = g_as1[s0 * H1 + head];
        float A1 = g_as1[s1 * H1 + head];
        float A2 = g_as1[s2 * H1 + head];
        float A3 = g_as1[s3 * H1 + head];
        const float4* p0 = (const float4*)(g_h1 + (size_t)s0 * C1 + c0);
        const float4* p1 = (const float4*)(g_h1 + (size_t)s1 * C1 + c0);
        const float4* p2 = (const float4*)(g_h1 + (size_t)s2 * C1 + c0);
        const float4* p3 = (const float4*)(g_h1 + (size_t)s3 * C1 + c0);
        float4 a0 = p0[0], b0 = p0[1];
        float4 a1 = p1[0], b1v = p1[1];
        float4 a2 = p2[0], b2v = p2[1];
        float4 a3 = p3[0], b3v = p3[1];
        float w0 = __expf(lrelu(A0 + adh) - mh) * invh;
        float w1 = __expf(lrelu(A1 + adh) - mh) * invh;
        float w2 = __expf(lrelu(A2 + adh) - mh) * invh;
        float w3 = __expf(lrelu(A3 + adh) - mh) * invh;
        acc[0] += w0 * a0.x + w1 * a1.x + w2 * a2.x + w3 * a3.x;
        acc[1] += w0 * a0.y + w1 * a1.y + w2 * a2.y + w3 * a3.y;
        acc[2] += w0 * a0.z + w1 * a1.z + w2 * a2.z + w3 * a3.z;
        acc[3] += w0 * a0.w + w1 * a1.w + w2 * a2.w + w3 * a3.w;
        acc[4] += w0 * b0.x + w1 * b1v.x + w2 * b2v.x + w3 * b3v.x;
        acc[5] += w0 * b0.y + w1 * b1v.y + w2 * b2v.y + w3 * b3v.y;
        acc[6] += w0 * b0.z + w1 * b1v.z + w2 * b2v.z + w3 * b3v.z;
        acc[7] += w0 * b0.w + w1 * b1v.w + w2 * b2v.w + w3 * b3v.w;
    }
    for (; i < end; i++) {
        int s = g_csrc[i];
        float asv = g_as1[s * H1 + head];
        float wgt = __expf(lrelu(asv + adh) - mh) * invh;
        const float4* hp = (const float4*)(g_h1 + (size_t)s * C1 + c0);
        float4 a = hp[0], b = hp[1];
        acc[0] += wgt * a.x; acc[1] += wgt * a.y;
        acc[2] += wgt * a.z; acc[3] += wgt * a.w;
        acc[4] += wgt * b.x; acc[5] += wgt * b.y;
        acc[6] += wgt * b.z; acc[7] += wgt * b.w;
    }
    float4 o0, o1;
    o0.x = fmaxf(acc[0] + b1[c0 + 0], 0.f);
    o0.y = fmaxf(acc[1] + b1[c0 + 1], 0.f);
    o0.z = fmaxf(acc[2] + b1[c0 + 2], 0.f);
    o0.w = fmaxf(acc[3] + b1[c0 + 3], 0.f);
    o1.x = fmaxf(acc[4] + b1[c0 + 4], 0.f);
    o1.y = fmaxf(acc[5] + b1[c0 + 5], 0.f);
    o1.z = fmaxf(acc[6] + b1[c0 + 6], 0.f);
    o1.w = fmaxf(acc[7] + b1[c0 + 7], 0.f);
    *(float4*)(outp) = o0;
    *(float4*)(outp + 4) = o1;
}

// ---------------- layer-2 aggregation: warp per dst node -------------------
__global__ void __launch_bounds__(256) k_agg2(const float* __restrict__ b2,
                                              float* __restrict__ out) {
    int wid = (blockIdx.x * blockDim.x + threadIdx.x) >> 5;
    int lane = threadIdx.x & 31;
    if (wid >= NN) return;
    int beg = g_offs[wid], end = g_offs[wid + 1];
    int c0 = lane * 2;
    float* outp = out + (size_t)wid * CIN + c0;
    if (beg == end) {
        outp[0] = b2[c0];
        outp[1] = b2[c0 + 1];
        return;
    }
    float ad = g_ad2[wid];
    float m = NEGINF, ds = 0.f;
    for (int i = beg + lane; i < end; i += 32) {
        int s = g_csrc[i];
        float ev = lrelu(g_as2[s] + ad);
        if (ev > m) {
            ds = ds * __expf(m - ev) + 1.f;
            m = ev;
        } else {
            ds += __expf(ev - m);
        }
    }
#pragma unroll
    for (int off = 16; off; off >>= 1) {
        float mo = __shfl_xor_sync(0xffffffffu, m, off);
        float d_o = __shfl_xor_sync(0xffffffffu, ds, off);
        float M = fmaxf(m, mo);
        float nd = 0.f;
        if (ds > 0.f) nd += ds * __expf(m - M);
        if (d_o > 0.f) nd += d_o * __expf(mo - M);
        m = M; ds = nd;
    }
    float inv = 1.f / ds;
    float acc0 = 0.f, acc1 = 0.f;
    int i = beg;
    for (; i + 4 <= end; i += 4) {
        int s0 = g_csrc[i], s1 = g_csrc[i + 1], s2 = g_csrc[i + 2], s3 = g_csrc[i + 3];
        float e0 = g_as2[s0], e1 = g_as2[s1], e2 = g_as2[s2], e3 = g_as2[s3];
        float2 v0 = *(const float2*)(g_h2 + (size_t)s0 * CIN + c0);
        float2 v1 = *(const float2*)(g_h2 + (size_t)s1 * CIN + c0);
        float2 v2 = *(const float2*)(g_h2 + (size_t)s2 * CIN + c0);
        float2 v3 = *(const float2*)(g_h2 + (size_t)s3 * CIN + c0);
        float w0 = __expf(lrelu(e0 + ad) - m) * inv;
        float w1 = __expf(lrelu(e1 + ad) - m) * inv;
        float w2 = __expf(lrelu(e2 + ad) - m) * inv;
        float w3 = __expf(lrelu(e3 + ad) - m) * inv;
        acc0 += w0 * v0.x + w1 * v1.x + w2 * v2.x + w3 * v3.x;
        acc1 += w0 * v0.y + w1 * v1.y + w2 * v2.y + w3 * v3.y;
    }
    for (; i < end; i++) {
        int s = g_csrc[i];
        float wgt = __expf(lrelu(g_as2[s] + ad) - m) * inv;
        float2 v = *(const float2*)(g_h2 + (size_t)s * CIN + c0);
        acc0 += wgt * v.x;
        acc1 += wgt * v.y;
    }
    outp[0] = acc0 + b2[c0];
    outp[1] = acc1 + b2[c0 + 1];
}

// ---------------- launcher -------------------------------------------------
extern "C" void kernel_launch(void* const* d_in, const int* in_sizes, int n_in,
                              void* d_out, int out_size) {
    const float* x    = (const float*)d_in[0];
    const int*   ei   = (const int*)d_in[1];   // int32 (JAX x64 disabled)
    const float* W1   = (const float*)d_in[2];
    const float* as1  = (const float*)d_in[3];
    const float* ad1  = (const float*)d_in[4];
    const float* b1   = (const float*)d_in[5];
    const float* W2   = (const float*)d_in[6];
    const float* as2  = (const float*)d_in[7];
    const float* ad2  = (const float*)d_in[8];
    const float* b2   = (const float*)d_in[9];
    float* out = (float*)d_out;

    k_zero_deg<<<(NN + 255) / 256, 256>>>();
    k_count<<<(EE + 255) / 256, 256>>>(ei);
    k_scan1<<<(NN + 1023) / 1024, 1024>>>();
    k_scan2<<<1, 64>>>();
    k_scan3<<<(NN + 255) / 256, 256>>>();
    k_scatter<<<(EE + 255) / 256, 256>>>(ei);

    k_gemm1<<<(NN + 63) / 64, 256>>>(x, W1);
    k_attn1<<<(NN + 7) / 8, 256>>>(as1, ad1);
    k_agg1<<<(NN + 7) / 8, 256>>>(b1);

    k_gemm2<<<(NN + 127) / 128, 256>>>(W2);
    k_attn2<<<(NN + 7) / 8, 256>>>(as2, ad2);
    k_agg2<<<(NN + 7) / 8, 256>>>(b2, out);
}

// round 4
// speedup vs baseline: 1.7377x; 1.1770x over previous
#include <cuda_runtime.h>
#include <cuda_bf16.h>

#define NN 50000
#define EE 800000
#define CIN 64
#define H1 4
#define C1 256   // H1*64
#define NEG 0.2f
#define NEGINF (-1e30f)

// ---------------- device scratch (no runtime allocation allowed) -----------
__device__ __nv_bfloat16 g_h1b[NN * C1]; // layer1 linear output, bf16 (gather path)
__device__ float g_h1r[NN * C1];   // relu(aggregated layer1) = layer2 input
__device__ float g_as1[NN * H1];
__device__ float g_ad1[NN * H1];
__device__ float g_h2[NN * CIN];   // layer2 linear output
__device__ float g_as2[NN];
__device__ float g_ad2[NN];
__device__ int   g_deg[NN];
__device__ int   g_offs[NN + 1];
__device__ int   g_cur[NN];
__device__ int   g_csrc[EE];       // CSR-by-dst: src node ids
__device__ int   g_part[64];       // scan block partials

__device__ __forceinline__ int clampN(int v) {
    return v < 0 ? 0 : (v >= NN ? NN - 1 : v);
}

// ---------------- packed f32x2 helpers (Blackwell FFMA2) -------------------
__device__ __forceinline__ unsigned long long pk2(float x, float y) {
    unsigned long long r;
    asm("mov.b64 %0, {%1, %2};" : "=l"(r)
        : "r"(__float_as_uint(x)), "r"(__float_as_uint(y)));
    return r;
}
__device__ __forceinline__ void upk2(unsigned long long v, float &x, float &y) {
    unsigned int lo, hi;
    asm("mov.b64 {%0, %1}, %2;" : "=r"(lo), "=r"(hi) : "l"(v));
    x = __uint_as_float(lo); y = __uint_as_float(hi);
}
__device__ __forceinline__ void fma2(unsigned long long &d,
                                     unsigned long long a,
                                     unsigned long long b) {
    asm("fma.rn.f32x2 %0, %1, %2, %0;" : "+l"(d) : "l"(a), "l"(b));
}

// ---------------- CSR construction ----------------------------------------
__global__ void k_zero_deg() {
    int i = blockIdx.x * blockDim.x + threadIdx.x;
    if (i < NN) g_deg[i] = 0;
}

__global__ void k_count(const int* __restrict__ ei) {
    int e = blockIdx.x * blockDim.x + threadIdx.x;
    if (e < EE) atomicAdd(&g_deg[clampN(ei[EE + e])], 1);
}

// 3-stage scan: block-local inclusive -> partial scan -> add-back
__global__ void __launch_bounds__(1024) k_scan1() {
    __shared__ int wsum[32];
    int t = threadIdx.x, b = blockIdx.x;
    int i = b * 1024 + t;
    int lane = t & 31, w = t >> 5;
    int v = (i < NN) ? g_deg[i] : 0;
    int x = v;
#pragma unroll
    for (int off = 1; off < 32; off <<= 1) {
        int u = __shfl_up_sync(0xffffffffu, x, off);
        if (lane >= off) x += u;
    }
    if (lane == 31) wsum[w] = x;
    __syncthreads();
    if (w == 0) {
        int s = wsum[lane];
#pragma unroll
        for (int off = 1; off < 32; off <<= 1) {
            int u = __shfl_up_sync(0xffffffffu, s, off);
            if (lane >= off) s += u;
        }
        wsum[lane] = s;
    }
    __syncthreads();
    int incl = x + (w > 0 ? wsum[w - 1] : 0);
    if (i < NN) g_offs[i + 1] = incl;     // block-local inclusive
    if (t == 1023) g_part[b] = incl;
}

__global__ void k_scan2() {   // 1 block, 64 threads; 49 partials
    __shared__ int sm[64];
    int t = threadIdx.x;
    sm[t] = (t < 49) ? g_part[t] : 0;
    __syncthreads();
#pragma unroll
    for (int off = 1; off < 64; off <<= 1) {
        int u = (t >= off) ? sm[t - off] : 0;
        __syncthreads();
        sm[t] += u;
        __syncthreads();
    }
    if (t < 49) g_part[t] = t ? sm[t - 1] : 0;   // exclusive
}

__global__ void k_scan3() {
    int i = blockIdx.x * blockDim.x + threadIdx.x;
    if (i == 0) g_offs[0] = 0;
    if (i < NN) {
        int v = g_offs[i + 1] + g_part[i >> 10];
        g_offs[i + 1] = v;
        g_cur[i] = v - g_deg[i];
    }
}

__global__ void k_scatter(const int* __restrict__ ei) {
    int e = blockIdx.x * blockDim.x + threadIdx.x;
    if (e < EE) {
        int d = clampN(ei[EE + e]);
        int s = clampN(ei[e]);
        int p = atomicAdd(&g_cur[d], 1);
        g_csrc[p] = s;
    }
}

// ---------------- GEMM 1: h1 = x[N,64] @ W1[64,256] ------------------------
// Block: 64 rows x 256 cols; thread: 8 rows x 8 cols (4 f32x2 col-pairs).
// Epilogue: bf16 store of h1 + fused per-head attention scalars (as1/ad1).
__global__ void __launch_bounds__(256) k_gemm1(const float* __restrict__ x,
                                               const float* __restrict__ W1,
                                               const float* __restrict__ att_s,
                                               const float* __restrict__ att_d) {
    __shared__ float sx[64 * 32];    // [row][kchunk]  8KB
    __shared__ float sW[32 * 256];   // [k][col]      32KB
    int t = threadIdx.x;
    int row0 = blockIdx.x * 64;
    int cg = t & 31, rg = t >> 5;
    unsigned long long acc[8][4];
#pragma unroll
    for (int m = 0; m < 8; m++)
#pragma unroll
        for (int c = 0; c < 4; c++) acc[m][c] = 0ull;

    for (int kc = 0; kc < 2; kc++) {
        __syncthreads();
        {
            float4* s4 = (float4*)sx;
#pragma unroll
            for (int q = 0; q < 2; q++) {
                int idx = t + q * 256;           // 0..511
                int row = idx >> 3, j = idx & 7;
                float4 v = make_float4(0.f, 0.f, 0.f, 0.f);
                if (row0 + row < NN)
                    v = *(const float4*)(x + (size_t)(row0 + row) * 64 + kc * 32 + j * 4);
                s4[idx] = v;
            }
            float4* w4 = (float4*)sW;
            const float4* wg = (const float4*)(W1 + kc * 32 * 256);
#pragma unroll
            for (int q = 0; q < 8; q++) w4[t + q * 256] = wg[t + q * 256];
        }
        __syncthreads();
        const float* xrow = sx + rg * 8 * 32;
#pragma unroll 2
        for (int k4 = 0; k4 < 8; k4++) {
            float4 xq[8];
#pragma unroll
            for (int m = 0; m < 8; m++)
                xq[m] = *(const float4*)(xrow + m * 32 + k4 * 4);
#pragma unroll
            for (int j = 0; j < 4; j++) {
                const ulonglong2* wp =
                    (const ulonglong2*)(sW + (k4 * 4 + j) * 256 + cg * 8);
                ulonglong2 wa = wp[0];
                ulonglong2 wb = wp[1];
#pragma unroll
                for (int m = 0; m < 8; m++) {
                    float xs = (j == 0) ? xq[m].x : (j == 1) ? xq[m].y
                             : (j == 2) ? xq[m].z : xq[m].w;
                    unsigned long long xd = pk2(xs, xs);
                    fma2(acc[m][0], xd, wa.x);
                    fma2(acc[m][1], xd, wa.y);
                    fma2(acc[m][2], xd, wb.x);
                    fma2(acc[m][3], xd, wb.y);
                }
            }
        }
    }
    // epilogue: bf16 store + fused attention scalar reduction
    int cb = cg * 8;
    float asv[8], adv[8];
#pragma unroll
    for (int q = 0; q < 8; q++) { asv[q] = att_s[cb + q]; adv[q] = att_d[cb + q]; }
#pragma unroll
    for (int m = 0; m < 8; m++) {
        int row = row0 + rg * 8 + m;
        float v[8];
        upk2(acc[m][0], v[0], v[1]);
        upk2(acc[m][1], v[2], v[3]);
        upk2(acc[m][2], v[4], v[5]);
        upk2(acc[m][3], v[6], v[7]);
        float ps = 0.f, pd = 0.f;
#pragma unroll
        for (int q = 0; q < 8; q++) { ps += v[q] * asv[q]; pd += v[q] * adv[q]; }
        // reduce within 8-lane group = one head (cols h*64..h*64+63)
#pragma unroll
        for (int off = 4; off; off >>= 1) {
            ps += __shfl_xor_sync(0xffffffffu, ps, off);
            pd += __shfl_xor_sync(0xffffffffu, pd, off);
        }
        if (row < NN) {
            __nv_bfloat162 p0 = __floats2bfloat162_rn(v[0], v[1]);
            __nv_bfloat162 p1 = __floats2bfloat162_rn(v[2], v[3]);
            __nv_bfloat162 p2 = __floats2bfloat162_rn(v[4], v[5]);
            __nv_bfloat162 p3 = __floats2bfloat162_rn(v[6], v[7]);
            uint4 u;
            u.x = *reinterpret_cast<unsigned*>(&p0);
            u.y = *reinterpret_cast<unsigned*>(&p1);
            u.z = *reinterpret_cast<unsigned*>(&p2);
            u.w = *reinterpret_cast<unsigned*>(&p3);
            *(uint4*)(g_h1b + (size_t)row * C1 + cb) = u;
            if ((cg & 7) == 0) {
                int h = cg >> 3;
                g_as1[row * H1 + h] = ps;
                g_ad1[row * H1 + h] = pd;
            }
        }
    }
}

// ---------------- GEMM 2: h2 = h1r[N,256] @ W2[256,64] ---------------------
// Block: 128 rows x 64 cols; thread: 8 rows x 4 cols (2 f32x2 col-pairs).
// Epilogue: fused attention scalars (as2/ad2) via 16-lane shfl reduce.
__global__ void __launch_bounds__(256) k_gemm2(const float* __restrict__ W2,
                                               const float* __restrict__ att_s,
                                               const float* __restrict__ att_d) {
    __shared__ float sx[128 * 32];   // 16KB
    __shared__ float sW[32 * 64];    //  8KB
    int t = threadIdx.x;
    int row0 = blockIdx.x * 128;
    int cg = t & 15, rg = t >> 4;
    unsigned long long acc[8][2];
#pragma unroll
    for (int m = 0; m < 8; m++) { acc[m][0] = 0ull; acc[m][1] = 0ull; }

    for (int kc = 0; kc < 8; kc++) {
        __syncthreads();
        {
            float4* s4 = (float4*)sx;
#pragma unroll
            for (int q = 0; q < 4; q++) {
                int idx = t + q * 256;           // 0..1023
                int row = idx >> 3, j = idx & 7;
                float4 v = make_float4(0.f, 0.f, 0.f, 0.f);
                if (row0 + row < NN)
                    v = *(const float4*)(g_h1r + (size_t)(row0 + row) * C1 + kc * 32 + j * 4);
                s4[idx] = v;
            }
            float4* w4 = (float4*)sW;
            const float4* wg = (const float4*)(W2 + kc * 32 * 64);
#pragma unroll
            for (int q = 0; q < 2; q++) w4[t + q * 256] = wg[t + q * 256];
        }
        __syncthreads();
        const float* xrow = sx + rg * 8 * 32;
#pragma unroll 2
        for (int k4 = 0; k4 < 8; k4++) {
            float4 xq[8];
#pragma unroll
            for (int m = 0; m < 8; m++)
                xq[m] = *(const float4*)(xrow + m * 32 + k4 * 4);
#pragma unroll
            for (int j = 0; j < 4; j++) {
                ulonglong2 wv =
                    *(const ulonglong2*)(sW + (k4 * 4 + j) * 64 + cg * 4);
#pragma unroll
                for (int m = 0; m < 8; m++) {
                    float xs = (j == 0) ? xq[m].x : (j == 1) ? xq[m].y
                             : (j == 2) ? xq[m].z : xq[m].w;
                    unsigned long long xd = pk2(xs, xs);
                    fma2(acc[m][0], xd, wv.x);
                    fma2(acc[m][1], xd, wv.y);
                }
            }
        }
    }
    int cb = cg * 4;
    float asv[4], adv[4];
#pragma unroll
    for (int q = 0; q < 4; q++) { asv[q] = att_s[cb + q]; adv[q] = att_d[cb + q]; }
#pragma unroll
    for (int m = 0; m < 8; m++) {
        int row = row0 + rg * 8 + m;
        float v[4];
        upk2(acc[m][0], v[0], v[1]);
        upk2(acc[m][1], v[2], v[3]);
        float ps = 0.f, pd = 0.f;
#pragma unroll
        for (int q = 0; q < 4; q++) { ps += v[q] * asv[q]; pd += v[q] * adv[q]; }
        // reduce over the 16 lanes (cg 0..15) holding this row
#pragma unroll
        for (int off = 8; off; off >>= 1) {
            ps += __shfl_xor_sync(0xffffffffu, ps, off);
            pd += __shfl_xor_sync(0xffffffffu, pd, off);
        }
        if (row < NN) {
            *(float4*)(g_h2 + (size_t)row * CIN + cb) =
                make_float4(v[0], v[1], v[2], v[3]);
            if (cg == 0) { g_as2[row] = ps; g_ad2[row] = pd; }
        }
    }
}

__device__ __forceinline__ float lrelu(float x) {
    return x > 0.f ? x : NEG * x;
}

// ---------------- layer-1 aggregation: warp per dst node -------------------
__global__ void __launch_bounds__(256) k_agg1(const float* __restrict__ b1) {
    int wid = (blockIdx.x * blockDim.x + threadIdx.x) >> 5;
    int lane = threadIdx.x & 31;
    if (wid >= NN) return;
    int beg = g_offs[wid], end = g_offs[wid + 1];
    int c0 = lane * 8;
    float* outp = g_h1r + (size_t)wid * C1 + c0;
    if (beg == end) {
        float4 o0, o1;
        o0.x = fmaxf(b1[c0 + 0], 0.f); o0.y = fmaxf(b1[c0 + 1], 0.f);
        o0.z = fmaxf(b1[c0 + 2], 0.f); o0.w = fmaxf(b1[c0 + 3], 0.f);
        o1.x = fmaxf(b1[c0 + 4], 0.f); o1.y = fmaxf(b1[c0 + 5], 0.f);
        o1.z = fmaxf(b1[c0 + 6], 0.f); o1.w = fmaxf(b1[c0 + 7], 0.f);
        *(float4*)(outp) = o0;
        *(float4*)(outp + 4) = o1;
        return;
    }
    float4 ad4 = *(const float4*)(g_ad1 + (size_t)wid * H1);
    float ad[4] = {ad4.x, ad4.y, ad4.z, ad4.w};
    float m[4], ds[4];
#pragma unroll
    for (int h = 0; h < 4; h++) { m[h] = NEGINF; ds[h] = 0.f; }
    for (int i = beg + lane; i < end; i += 32) {
        int s = g_csrc[i];
        float4 as4 = *(const float4*)(g_as1 + (size_t)s * H1);
        float e[4] = {as4.x + ad[0], as4.y + ad[1], as4.z + ad[2], as4.w + ad[3]};
#pragma unroll
        for (int h = 0; h < 4; h++) {
            float ev = lrelu(e[h]);
            if (ev > m[h]) {
                ds[h] = ds[h] * __expf(m[h] - ev) + 1.f;
                m[h] = ev;
            } else {
                ds[h] += __expf(ev - m[h]);
            }
        }
    }
#pragma unroll
    for (int off = 16; off; off >>= 1) {
#pragma unroll
        for (int h = 0; h < 4; h++) {
            float mo = __shfl_xor_sync(0xffffffffu, m[h], off);
            float d_o = __shfl_xor_sync(0xffffffffu, ds[h], off);
            float M = fmaxf(m[h], mo);
            float nd = 0.f;
            if (ds[h] > 0.f) nd += ds[h] * __expf(m[h] - M);
            if (d_o > 0.f)  nd += d_o * __expf(mo - M);
            m[h] = M; ds[h] = nd;
        }
    }
    int head = lane >> 3;
    float mh = m[head];
    float invh = 1.f / ds[head];
    float adh = ad[head];
    float acc[8];
#pragma unroll
    for (int q = 0; q < 8; q++) acc[q] = 0.f;
    int i = beg;
    // 4-way unrolled bf16 gather
    for (; i + 4 <= end; i += 4) {
        int s0 = g_csrc[i], s1 = g_csrc[i + 1], s2 = g_csrc[i + 2], s3 = g_csrc[i + 3];
        float A0 = g_as1[s0 * H1 + head];
        float A1 = g_as1[s1 * H1 + head];
        float A2 = g_as1[s2 * H1 + head];
        float A3 = g_as1[s3 * H1 + head];
        uint4 u0 = *(const uint4*)(g_h1b + (size_t)s0 * C1 + c0);
        uint4 u1 = *(const uint4*)(g_h1b + (size_t)s1 * C1 + c0);
        uint4 u2 = *(const uint4*)(g_h1b + (size_t)s2 * C1 + c0);
        uint4 u3 = *(const uint4*)(g_h1b + (size_t)s3 * C1 + c0);
        float w0 = __expf(lrelu(A0 + adh) - mh) * invh;
        float w1 = __expf(lrelu(A1 + adh) - mh) * invh;
        float w2 = __expf(lrelu(A2 + adh) - mh) * invh;
        float w3 = __expf(lrelu(A3 + adh) - mh) * invh;
#pragma unroll
        for (int q = 0; q < 4; q++) {
            unsigned uu0 = (&u0.x)[q], uu1 = (&u1.x)[q], uu2 = (&u2.x)[q], uu3 = (&u3.x)[q];
            float2 f0 = __bfloat1622float2(*reinterpret_cast<__nv_bfloat162*>(&uu0));
            float2 f1 = __bfloat1622float2(*reinterpret_cast<__nv_bfloat162*>(&uu1));
            float2 f2 = __bfloat1622float2(*reinterpret_cast<__nv_bfloat162*>(&uu2));
            float2 f3 = __bfloat1622float2(*reinterpret_cast<__nv_bfloat162*>(&uu3));
            acc[2 * q]     += w0 * f0.x + w1 * f1.x + w2 * f2.x + w3 * f3.x;
            acc[2 * q + 1] += w0 * f0.y + w1 * f1.y + w2 * f2.y + w3 * f3.y;
        }
    }
    for (; i < end; i++) {
        int s = g_csrc[i];
        float asv = g_as1[s * H1 + head];
        float wgt = __expf(lrelu(asv + adh) - mh) * invh;
        uint4 u = *(const uint4*)(g_h1b + (size_t)s * C1 + c0);
#pragma unroll
        for (int q = 0; q < 4; q++) {
            unsigned uu = (&u.x)[q];
            float2 f = __bfloat1622float2(*reinterpret_cast<__nv_bfloat162*>(&uu));
            acc[2 * q]     += wgt * f.x;
            acc[2 * q + 1] += wgt * f.y;
        }
    }
    float4 o0, o1;
    o0.x = fmaxf(acc[0] + b1[c0 + 0], 0.f);
    o0.y = fmaxf(acc[1] + b1[c0 + 1], 0.f);
    o0.z = fmaxf(acc[2] + b1[c0 + 2], 0.f);
    o0.w = fmaxf(acc[3] + b1[c0 + 3], 0.f);
    o1.x = fmaxf(acc[4] + b1[c0 + 4], 0.f);
    o1.y = fmaxf(acc[5] + b1[c0 + 5], 0.f);
    o1.z = fmaxf(acc[6] + b1[c0 + 6], 0.f);
    o1.w = fmaxf(acc[7] + b1[c0 + 7], 0.f);
    *(float4*)(outp) = o0;
    *(float4*)(outp + 4) = o1;
}

// ---------------- layer-2 aggregation: warp per dst node -------------------
__global__ void __launch_bounds__(256) k_agg2(const float* __restrict__ b2,
                                              float* __restrict__ out) {
    int wid = (blockIdx.x * blockDim.x + threadIdx.x) >> 5;
    int lane = threadIdx.x & 31;
    if (wid >= NN) return;
    int beg = g_offs[wid], end = g_offs[wid + 1];
    int c0 = lane * 2;
    float* outp = out + (size_t)wid * CIN + c0;
    if (beg == end) {
        outp[0] = b2[c0];
        outp[1] = b2[c0 + 1];
        return;
    }
    float ad = g_ad2[wid];
    float m = NEGINF, ds = 0.f;
    for (int i = beg + lane; i < end; i += 32) {
        int s = g_csrc[i];
        float ev = lrelu(g_as2[s] + ad);
        if (ev > m) {
            ds = ds * __expf(m - ev) + 1.f;
            m = ev;
        } else {
            ds += __expf(ev - m);
        }
    }
#pragma unroll
    for (int off = 16; off; off >>= 1) {
        float mo = __shfl_xor_sync(0xffffffffu, m, off);
        float d_o = __shfl_xor_sync(0xffffffffu, ds, off);
        float M = fmaxf(m, mo);
        float nd = 0.f;
        if (ds > 0.f) nd += ds * __expf(m - M);
        if (d_o > 0.f) nd += d_o * __expf(mo - M);
        m = M; ds = nd;
    }
    float inv = 1.f / ds;
    float acc0 = 0.f, acc1 = 0.f;
    int i = beg;
    for (; i + 4 <= end; i += 4) {
        int s0 = g_csrc[i], s1 = g_csrc[i + 1], s2 = g_csrc[i + 2], s3 = g_csrc[i + 3];
        float e0 = g_as2[s0], e1 = g_as2[s1], e2 = g_as2[s2], e3 = g_as2[s3];
        float2 v0 = *(const float2*)(g_h2 + (size_t)s0 * CIN + c0);
        float2 v1 = *(const float2*)(g_h2 + (size_t)s1 * CIN + c0);
        float2 v2 = *(const float2*)(g_h2 + (size_t)s2 * CIN + c0);
        float2 v3 = *(const float2*)(g_h2 + (size_t)s3 * CIN + c0);
        float w0 = __expf(lrelu(e0 + ad) - m) * inv;
        float w1 = __expf(lrelu(e1 + ad) - m) * inv;
        float w2 = __expf(lrelu(e2 + ad) - m) * inv;
        float w3 = __expf(lrelu(e3 + ad) - m) * inv;
        acc0 += w0 * v0.x + w1 * v1.x + w2 * v2.x + w3 * v3.x;
        acc1 += w0 * v0.y + w1 * v1.y + w2 * v2.y + w3 * v3.y;
    }
    for (; i < end; i++) {
        int s = g_csrc[i];
        float wgt = __expf(lrelu(g_as2[s] + ad) - m) * inv;
        float2 v = *(const float2*)(g_h2 + (size_t)s * CIN + c0);
        acc0 += wgt * v.x;
        acc1 += wgt * v.y;
    }
    outp[0] = acc0 + b2[c0];
    outp[1] = acc1 + b2[c0 + 1];
}

// ---------------- launcher -------------------------------------------------
extern "C" void kernel_launch(void* const* d_in, const int* in_sizes, int n_in,
                              void* d_out, int out_size) {
    const float* x    = (const float*)d_in[0];
    const int*   ei   = (const int*)d_in[1];   // int32 (JAX x64 disabled)
    const float* W1   = (const float*)d_in[2];
    const float* as1  = (const float*)d_in[3];
    const float* ad1  = (const float*)d_in[4];
    const float* b1   = (const float*)d_in[5];
    const float* W2   = (const float*)d_in[6];
    const float* as2  = (const float*)d_in[7];
    const float* ad2  = (const float*)d_in[8];
    const float* b2   = (const float*)d_in[9];
    float* out = (float*)d_out;

    k_zero_deg<<<(NN + 255) / 256, 256>>>();
    k_count<<<(EE + 255) / 256, 256>>>(ei);
    k_scan1<<<(NN + 1023) / 1024, 1024>>>();
    k_scan2<<<1, 64>>>();
    k_scan3<<<(NN + 255) / 256, 256>>>();
    k_scatter<<<(EE + 255) / 256, 256>>>(ei);

    k_gemm1<<<(NN + 63) / 64, 256>>>(x, W1, as1, ad1);
    k_agg1<<<(NN + 7) / 8, 256>>>(b1);

    k_gemm2<<<(NN + 127) / 128, 256>>>(W2, as2, ad2);
    k_agg2<<<(NN + 7) / 8, 256>>>(b2, out);
}

// round 5
// speedup vs baseline: 1.7583x; 1.0118x over previous
#include <cuda_runtime.h>
#include <cuda_fp16.h>

#define NN 50000
#define EE 800000
#define CIN 64
#define H1 4
#define C1 256   // H1*64
#define NEG 0.2f
#define NEGINF (-1e30f)

// ---------------- device scratch (no runtime allocation allowed) -----------
__device__ __half g_h1b[NN * C1];  // layer1 linear output, fp16 (gather path)
__device__ __half g_h1r[NN * C1];  // relu(aggregated layer1), fp16 = layer2 input
__device__ float g_as1[NN * H1];
__device__ float g_ad1[NN * H1];
__device__ __half g_h2[NN * CIN];  // layer2 linear output, fp16 (gather path)
__device__ float g_as2[NN];
__device__ float g_ad2[NN];
__device__ int   g_deg[NN];
__device__ int   g_offs[NN + 1];
__device__ int   g_cur[NN];
__device__ int   g_csrc[EE];       // CSR-by-dst: src node ids
__device__ int   g_part[64];       // scan block partials

__device__ __forceinline__ int clampN(int v) {
    return v < 0 ? 0 : (v >= NN ? NN - 1 : v);
}

// ---------------- packed f32x2 helpers (Blackwell FFMA2) -------------------
__device__ __forceinline__ unsigned long long pk2(float x, float y) {
    unsigned long long r;
    asm("mov.b64 %0, {%1, %2};" : "=l"(r)
        : "r"(__float_as_uint(x)), "r"(__float_as_uint(y)));
    return r;
}
__device__ __forceinline__ void upk2(unsigned long long v, float &x, float &y) {
    unsigned int lo, hi;
    asm("mov.b64 {%0, %1}, %2;" : "=r"(lo), "=r"(hi) : "l"(v));
    x = __uint_as_float(lo); y = __uint_as_float(hi);
}
__device__ __forceinline__ void fma2(unsigned long long &d,
                                     unsigned long long a,
                                     unsigned long long b) {
    asm("fma.rn.f32x2 %0, %1, %2, %0;" : "+l"(d) : "l"(a), "l"(b));
}

__device__ __forceinline__ float2 h2f2(unsigned u) {
    return __half22float2(*reinterpret_cast<__half2*>(&u));
}

// ---------------- CSR construction ----------------------------------------
__global__ void k_count(const int* __restrict__ ei) {
    int e4 = blockIdx.x * blockDim.x + threadIdx.x;
    if (e4 < EE / 4) {
        int4 d = *(const int4*)(ei + EE + 4 * e4);
        atomicAdd(&g_deg[clampN(d.x)], 1);
        atomicAdd(&g_deg[clampN(d.y)], 1);
        atomicAdd(&g_deg[clampN(d.z)], 1);
        atomicAdd(&g_deg[clampN(d.w)], 1);
    }
}

// 3-stage scan: block-local inclusive -> partial scan -> add-back
__global__ void __launch_bounds__(1024) k_scan1() {
    __shared__ int wsum[32];
    int t = threadIdx.x, b = blockIdx.x;
    int i = b * 1024 + t;
    int lane = t & 31, w = t >> 5;
    int v = (i < NN) ? g_deg[i] : 0;
    int x = v;
#pragma unroll
    for (int off = 1; off < 32; off <<= 1) {
        int u = __shfl_up_sync(0xffffffffu, x, off);
        if (lane >= off) x += u;
    }
    if (lane == 31) wsum[w] = x;
    __syncthreads();
    if (w == 0) {
        int s = wsum[lane];
#pragma unroll
        for (int off = 1; off < 32; off <<= 1) {
            int u = __shfl_up_sync(0xffffffffu, s, off);
            if (lane >= off) s += u;
        }
        wsum[lane] = s;
    }
    __syncthreads();
    int incl = x + (w > 0 ? wsum[w - 1] : 0);
    if (i < NN) g_offs[i + 1] = incl;     // block-local inclusive
    if (t == 1023) g_part[b] = incl;
}

__global__ void k_scan2() {   // 1 block, 64 threads; 49 partials
    __shared__ int sm[64];
    int t = threadIdx.x;
    sm[t] = (t < 49) ? g_part[t] : 0;
    __syncthreads();
#pragma unroll
    for (int off = 1; off < 64; off <<= 1) {
        int u = (t >= off) ? sm[t - off] : 0;
        __syncthreads();
        sm[t] += u;
        __syncthreads();
    }
    if (t < 49) g_part[t] = t ? sm[t - 1] : 0;   // exclusive
}

__global__ void k_scan3() {
    int i = blockIdx.x * blockDim.x + threadIdx.x;
    if (i == 0) g_offs[0] = 0;
    if (i < NN) {
        int v = g_offs[i + 1] + g_part[i >> 10];
        g_offs[i + 1] = v;
        g_cur[i] = v - g_deg[i];
    }
}

__global__ void k_scatter(const int* __restrict__ ei) {
    int e4 = blockIdx.x * blockDim.x + threadIdx.x;
    if (e4 < EE / 4) {
        int4 s = *(const int4*)(ei + 4 * e4);
        int4 d = *(const int4*)(ei + EE + 4 * e4);
        int p0 = atomicAdd(&g_cur[clampN(d.x)], 1);
        int p1 = atomicAdd(&g_cur[clampN(d.y)], 1);
        int p2 = atomicAdd(&g_cur[clampN(d.z)], 1);
        int p3 = atomicAdd(&g_cur[clampN(d.w)], 1);
        g_csrc[p0] = clampN(s.x);
        g_csrc[p1] = clampN(s.y);
        g_csrc[p2] = clampN(s.z);
        g_csrc[p3] = clampN(s.w);
    }
}

// ---------------- GEMM 1: h1 = x[N,64] @ W1[64,256] ------------------------
// Block: 64 rows x 256 cols; thread: 8 rows x 8 cols (4 f32x2 col-pairs).
// Epilogue: fp16 store of h1 + fused per-head attention scalars (as1/ad1).
__global__ void __launch_bounds__(256) k_gemm1(const float* __restrict__ x,
                                               const float* __restrict__ W1,
                                               const float* __restrict__ att_s,
                                               const float* __restrict__ att_d) {
    __shared__ float sx[64 * 32];    // [row][kchunk]  8KB
    __shared__ float sW[32 * 256];   // [k][col]      32KB
    int t = threadIdx.x;
    int row0 = blockIdx.x * 64;
    int cg = t & 31, rg = t >> 5;
    unsigned long long acc[8][4];
#pragma unroll
    for (int m = 0; m < 8; m++)
#pragma unroll
        for (int c = 0; c < 4; c++) acc[m][c] = 0ull;

    for (int kc = 0; kc < 2; kc++) {
        __syncthreads();
        {
            float4* s4 = (float4*)sx;
#pragma unroll
            for (int q = 0; q < 2; q++) {
                int idx = t + q * 256;           // 0..511
                int row = idx >> 3, j = idx & 7;
                float4 v = make_float4(0.f, 0.f, 0.f, 0.f);
                if (row0 + row < NN)
                    v = *(const float4*)(x + (size_t)(row0 + row) * 64 + kc * 32 + j * 4);
                s4[idx] = v;
            }
            float4* w4 = (float4*)sW;
            const float4* wg = (const float4*)(W1 + kc * 32 * 256);
#pragma unroll
            for (int q = 0; q < 8; q++) w4[t + q * 256] = wg[t + q * 256];
        }
        __syncthreads();
        const float* xrow = sx + rg * 8 * 32;
#pragma unroll 2
        for (int k4 = 0; k4 < 8; k4++) {
            float4 xq[8];
#pragma unroll
            for (int m = 0; m < 8; m++)
                xq[m] = *(const float4*)(xrow + m * 32 + k4 * 4);
#pragma unroll
            for (int j = 0; j < 4; j++) {
                const ulonglong2* wp =
                    (const ulonglong2*)(sW + (k4 * 4 + j) * 256 + cg * 8);
                ulonglong2 wa = wp[0];
                ulonglong2 wb = wp[1];
#pragma unroll
                for (int m = 0; m < 8; m++) {
                    float xs = (j == 0) ? xq[m].x : (j == 1) ? xq[m].y
                             : (j == 2) ? xq[m].z : xq[m].w;
                    unsigned long long xd = pk2(xs, xs);
                    fma2(acc[m][0], xd, wa.x);
                    fma2(acc[m][1], xd, wa.y);
                    fma2(acc[m][2], xd, wb.x);
                    fma2(acc[m][3], xd, wb.y);
                }
            }
        }
    }
    // epilogue: fp16 store + fused attention scalar reduction
    int cb = cg * 8;
    float asv[8], adv[8];
#pragma unroll
    for (int q = 0; q < 8; q++) { asv[q] = att_s[cb + q]; adv[q] = att_d[cb + q]; }
#pragma unroll
    for (int m = 0; m < 8; m++) {
        int row = row0 + rg * 8 + m;
        float v[8];
        upk2(acc[m][0], v[0], v[1]);
        upk2(acc[m][1], v[2], v[3]);
        upk2(acc[m][2], v[4], v[5]);
        upk2(acc[m][3], v[6], v[7]);
        float ps = 0.f, pd = 0.f;
#pragma unroll
        for (int q = 0; q < 8; q++) { ps += v[q] * asv[q]; pd += v[q] * adv[q]; }
        // reduce within 8-lane group = one head (cols h*64..h*64+63)
#pragma unroll
        for (int off = 4; off; off >>= 1) {
            ps += __shfl_xor_sync(0xffffffffu, ps, off);
            pd += __shfl_xor_sync(0xffffffffu, pd, off);
        }
        if (row < NN) {
            __half2 p0 = __floats2half2_rn(v[0], v[1]);
            __half2 p1 = __floats2half2_rn(v[2], v[3]);
            __half2 p2 = __floats2half2_rn(v[4], v[5]);
            __half2 p3 = __floats2half2_rn(v[6], v[7]);
            uint4 u;
            u.x = *reinterpret_cast<unsigned*>(&p0);
            u.y = *reinterpret_cast<unsigned*>(&p1);
            u.z = *reinterpret_cast<unsigned*>(&p2);
            u.w = *reinterpret_cast<unsigned*>(&p3);
            *(uint4*)(g_h1b + (size_t)row * C1 + cb) = u;
            if ((cg & 7) == 0) {
                int h = cg >> 3;
                g_as1[row * H1 + h] = ps;
                g_ad1[row * H1 + h] = pd;
            }
        }
    }
}

// ---------------- GEMM 2: h2 = h1r[N,256] @ W2[256,64] ---------------------
// Block: 128 rows x 64 cols; thread: 8 rows x 4 cols (2 f32x2 col-pairs).
// Input h1r is fp16 (converted to fp32 in smem); epilogue fuses as2/ad2.
__global__ void __launch_bounds__(256) k_gemm2(const float* __restrict__ W2,
                                               const float* __restrict__ att_s,
                                               const float* __restrict__ att_d) {
    __shared__ float sx[128 * 32];   // 16KB
    __shared__ float sW[32 * 64];    //  8KB
    int t = threadIdx.x;
    int row0 = blockIdx.x * 128;
    int cg = t & 15, rg = t >> 4;
    unsigned long long acc[8][2];
#pragma unroll
    for (int m = 0; m < 8; m++) { acc[m][0] = 0ull; acc[m][1] = 0ull; }

    for (int kc = 0; kc < 8; kc++) {
        __syncthreads();
        {
            float4* s4 = (float4*)sx;
#pragma unroll
            for (int q = 0; q < 4; q++) {
                int idx = t + q * 256;           // 0..1023
                int row = idx >> 3, j = idx & 7; // j: 4-half chunk
                float4 v = make_float4(0.f, 0.f, 0.f, 0.f);
                if (row0 + row < NN) {
                    uint2 hv = *(const uint2*)(g_h1r + (size_t)(row0 + row) * C1 + kc * 32 + j * 4);
                    float2 f0 = h2f2(hv.x);
                    float2 f1 = h2f2(hv.y);
                    v = make_float4(f0.x, f0.y, f1.x, f1.y);
                }
                s4[idx] = v;
            }
            float4* w4 = (float4*)sW;
            const float4* wg = (const float4*)(W2 + kc * 32 * 64);
#pragma unroll
            for (int q = 0; q < 2; q++) w4[t + q * 256] = wg[t + q * 256];
        }
        __syncthreads();
        const float* xrow = sx + rg * 8 * 32;
#pragma unroll 2
        for (int k4 = 0; k4 < 8; k4++) {
            float4 xq[8];
#pragma unroll
            for (int m = 0; m < 8; m++)
                xq[m] = *(const float4*)(xrow + m * 32 + k4 * 4);
#pragma unroll
            for (int j = 0; j < 4; j++) {
                ulonglong2 wv =
                    *(const ulonglong2*)(sW + (k4 * 4 + j) * 64 + cg * 4);
#pragma unroll
                for (int m = 0; m < 8; m++) {
                    float xs = (j == 0) ? xq[m].x : (j == 1) ? xq[m].y
                             : (j == 2) ? xq[m].z : xq[m].w;
                    unsigned long long xd = pk2(xs, xs);
                    fma2(acc[m][0], xd, wv.x);
                    fma2(acc[m][1], xd, wv.y);
                }
            }
        }
    }
    int cb = cg * 4;
    float asv[4], adv[4];
#pragma unroll
    for (int q = 0; q < 4; q++) { asv[q] = att_s[cb + q]; adv[q] = att_d[cb + q]; }
#pragma unroll
    for (int m = 0; m < 8; m++) {
        int row = row0 + rg * 8 + m;
        float v[4];
        upk2(acc[m][0], v[0], v[1]);
        upk2(acc[m][1], v[2], v[3]);
        float ps = 0.f, pd = 0.f;
#pragma unroll
        for (int q = 0; q < 4; q++) { ps += v[q] * asv[q]; pd += v[q] * adv[q]; }
#pragma unroll
        for (int off = 8; off; off >>= 1) {
            ps += __shfl_xor_sync(0xffffffffu, ps, off);
            pd += __shfl_xor_sync(0xffffffffu, pd, off);
        }
        if (row < NN) {
            __half2 p0 = __floats2half2_rn(v[0], v[1]);
            __half2 p1 = __floats2half2_rn(v[2], v[3]);
            uint2 u;
            u.x = *reinterpret_cast<unsigned*>(&p0);
            u.y = *reinterpret_cast<unsigned*>(&p1);
            *(uint2*)(g_h2 + (size_t)row * CIN + cb) = u;
            if (cg == 0) { g_as2[row] = ps; g_ad2[row] = pd; }
        }
    }
}

__device__ __forceinline__ float lrelu(float x) {
    return x > 0.f ? x : NEG * x;
}

// ---------------- layer-1 aggregation: warp per dst node -------------------
__global__ void __launch_bounds__(256) k_agg1(const float* __restrict__ b1) {
    int wid = (blockIdx.x * blockDim.x + threadIdx.x) >> 5;
    int lane = threadIdx.x & 31;
    if (wid >= NN) return;
    int beg = g_offs[wid], end = g_offs[wid + 1];
    int c0 = lane * 8;
    __half* outp = g_h1r + (size_t)wid * C1 + c0;
    float bb[8];
#pragma unroll
    for (int q = 0; q < 8; q++) bb[q] = b1[c0 + q];
    if (beg == end) {
        __half2 p0 = __floats2half2_rn(fmaxf(bb[0], 0.f), fmaxf(bb[1], 0.f));
        __half2 p1 = __floats2half2_rn(fmaxf(bb[2], 0.f), fmaxf(bb[3], 0.f));
        __half2 p2 = __floats2half2_rn(fmaxf(bb[4], 0.f), fmaxf(bb[5], 0.f));
        __half2 p3 = __floats2half2_rn(fmaxf(bb[6], 0.f), fmaxf(bb[7], 0.f));
        uint4 u;
        u.x = *reinterpret_cast<unsigned*>(&p0);
        u.y = *reinterpret_cast<unsigned*>(&p1);
        u.z = *reinterpret_cast<unsigned*>(&p2);
        u.w = *reinterpret_cast<unsigned*>(&p3);
        *(uint4*)outp = u;
        return;
    }
    float4 ad4 = *(const float4*)(g_ad1 + (size_t)wid * H1);
    float ad[4] = {ad4.x, ad4.y, ad4.z, ad4.w};
    float m[4], ds[4];
#pragma unroll
    for (int h = 0; h < 4; h++) { m[h] = NEGINF; ds[h] = 0.f; }
    for (int i = beg + lane; i < end; i += 32) {
        int s = g_csrc[i];
        float4 as4 = *(const float4*)(g_as1 + (size_t)s * H1);
        float e[4] = {as4.x + ad[0], as4.y + ad[1], as4.z + ad[2], as4.w + ad[3]};
#pragma unroll
        for (int h = 0; h < 4; h++) {
            float ev = lrelu(e[h]);
            if (ev > m[h]) {
                ds[h] = ds[h] * __expf(m[h] - ev) + 1.f;
                m[h] = ev;
            } else {
                ds[h] += __expf(ev - m[h]);
            }
        }
    }
#pragma unroll
    for (int off = 16; off; off >>= 1) {
#pragma unroll
        for (int h = 0; h < 4; h++) {
            float mo = __shfl_xor_sync(0xffffffffu, m[h], off);
            float d_o = __shfl_xor_sync(0xffffffffu, ds[h], off);
            float M = fmaxf(m[h], mo);
            float nd = 0.f;
            if (ds[h] > 0.f) nd += ds[h] * __expf(m[h] - M);
            if (d_o > 0.f)  nd += d_o * __expf(mo - M);
            m[h] = M; ds[h] = nd;
        }
    }
    int head = lane >> 3;
    float mh = m[head];
    float invh = 1.f / ds[head];
    float adh = ad[head];
    float acc[8];
#pragma unroll
    for (int q = 0; q < 8; q++) acc[q] = 0.f;
    int i = beg;
    // 4-way unrolled fp16 gather
    for (; i + 4 <= end; i += 4) {
        int s0 = g_csrc[i], s1 = g_csrc[i + 1], s2 = g_csrc[i + 2], s3 = g_csrc[i + 3];
        float A0 = g_as1[s0 * H1 + head];
        float A1 = g_as1[s1 * H1 + head];
        float A2 = g_as1[s2 * H1 + head];
        float A3 = g_as1[s3 * H1 + head];
        uint4 u0 = *(const uint4*)(g_h1b + (size_t)s0 * C1 + c0);
        uint4 u1 = *(const uint4*)(g_h1b + (size_t)s1 * C1 + c0);
        uint4 u2 = *(const uint4*)(g_h1b + (size_t)s2 * C1 + c0);
        uint4 u3 = *(const uint4*)(g_h1b + (size_t)s3 * C1 + c0);
        float w0 = __expf(lrelu(A0 + adh) - mh) * invh;
        float w1 = __expf(lrelu(A1 + adh) - mh) * invh;
        float w2 = __expf(lrelu(A2 + adh) - mh) * invh;
        float w3 = __expf(lrelu(A3 + adh) - mh) * invh;
#pragma unroll
        for (int q = 0; q < 4; q++) {
            float2 f0 = h2f2((&u0.x)[q]);
            float2 f1 = h2f2((&u1.x)[q]);
            float2 f2 = h2f2((&u2.x)[q]);
            float2 f3 = h2f2((&u3.x)[q]);
            acc[2 * q]     += w0 * f0.x + w1 * f1.x + w2 * f2.x + w3 * f3.x;
            acc[2 * q + 1] += w0 * f0.y + w1 * f1.y + w2 * f2.y + w3 * f3.y;
        }
    }
    for (; i < end; i++) {
        int s = g_csrc[i];
        float asv = g_as1[s * H1 + head];
        float wgt = __expf(lrelu(asv + adh) - mh) * invh;
        uint4 u = *(const uint4*)(g_h1b + (size_t)s * C1 + c0);
#pragma unroll
        for (int q = 0; q < 4; q++) {
            float2 f = h2f2((&u.x)[q]);
            acc[2 * q]     += wgt * f.x;
            acc[2 * q + 1] += wgt * f.y;
        }
    }
    __half2 p0 = __floats2half2_rn(fmaxf(acc[0] + bb[0], 0.f), fmaxf(acc[1] + bb[1], 0.f));
    __half2 p1 = __floats2half2_rn(fmaxf(acc[2] + bb[2], 0.f), fmaxf(acc[3] + bb[3], 0.f));
    __half2 p2 = __floats2half2_rn(fmaxf(acc[4] + bb[4], 0.f), fmaxf(acc[5] + bb[5], 0.f));
    __half2 p3 = __floats2half2_rn(fmaxf(acc[6] + bb[6], 0.f), fmaxf(acc[7] + bb[7], 0.f));
    uint4 u;
    u.x = *reinterpret_cast<unsigned*>(&p0);
    u.y = *reinterpret_cast<unsigned*>(&p1);
    u.z = *reinterpret_cast<unsigned*>(&p2);
    u.w = *reinterpret_cast<unsigned*>(&p3);
    *(uint4*)outp = u;
}

// ---------------- layer-2 aggregation: warp per dst node -------------------
__global__ void __launch_bounds__(256) k_agg2(const float* __restrict__ b2,
                                              float* __restrict__ out) {
    int wid = (blockIdx.x * blockDim.x + threadIdx.x) >> 5;
    int lane = threadIdx.x & 31;
    if (wid >= NN) return;
    int beg = g_offs[wid], end = g_offs[wid + 1];
    int c0 = lane * 2;
    float* outp = out + (size_t)wid * CIN + c0;
    float b0 = b2[c0], b1v = b2[c0 + 1];
    if (beg == end) {
        outp[0] = b0;
        outp[1] = b1v;
        return;
    }
    float ad = g_ad2[wid];
    float m = NEGINF, ds = 0.f;
    for (int i = beg + lane; i < end; i += 32) {
        int s = g_csrc[i];
        float ev = lrelu(g_as2[s] + ad);
        if (ev > m) {
            ds = ds * __expf(m - ev) + 1.f;
            m = ev;
        } else {
            ds += __expf(ev - m);
        }
    }
#pragma unroll
    for (int off = 16; off; off >>= 1) {
        float mo = __shfl_xor_sync(0xffffffffu, m, off);
        float d_o = __shfl_xor_sync(0xffffffffu, ds, off);
        float M = fmaxf(m, mo);
        float nd = 0.f;
        if (ds > 0.f) nd += ds * __expf(m - M);
        if (d_o > 0.f) nd += d_o * __expf(mo - M);
        m = M; ds = nd;
    }
    float inv = 1.f / ds;
    float acc0 = 0.f, acc1 = 0.f;
    int i = beg;
    for (; i + 4 <= end; i += 4) {
        int s0 = g_csrc[i], s1 = g_csrc[i + 1], s2 = g_csrc[i + 2], s3 = g_csrc[i + 3];
        float e0 = g_as2[s0], e1 = g_as2[s1], e2 = g_as2[s2], e3 = g_as2[s3];
        unsigned u0 = *(const unsigned*)(g_h2 + (size_t)s0 * CIN + c0);
        unsigned u1 = *(const unsigned*)(g_h2 + (size_t)s1 * CIN + c0);
        unsigned u2 = *(const unsigned*)(g_h2 + (size_t)s2 * CIN + c0);
        unsigned u3 = *(const unsigned*)(g_h2 + (size_t)s3 * CIN + c0);
        float w0 = __expf(lrelu(e0 + ad) - m) * inv;
        float w1 = __expf(lrelu(e1 + ad) - m) * inv;
        float w2 = __expf(lrelu(e2 + ad) - m) * inv;
        float w3 = __expf(lrelu(e3 + ad) - m) * inv;
        float2 v0 = h2f2(u0), v1 = h2f2(u1), v2 = h2f2(u2), v3 = h2f2(u3);
        acc0 += w0 * v0.x + w1 * v1.x + w2 * v2.x + w3 * v3.x;
        acc1 += w0 * v0.y + w1 * v1.y + w2 * v2.y + w3 * v3.y;
    }
    for (; i < end; i++) {
        int s = g_csrc[i];
        float wgt = __expf(lrelu(g_as2[s] + ad) - m) * inv;
        float2 v = h2f2(*(const unsigned*)(g_h2 + (size_t)s * CIN + c0));
        acc0 += wgt * v.x;
        acc1 += wgt * v.y;
    }
    outp[0] = acc0 + b0;
    outp[1] = acc1 + b1v;
}

// ---------------- launcher -------------------------------------------------
extern "C" void kernel_launch(void* const* d_in, const int* in_sizes, int n_in,
                              void* d_out, int out_size) {
    const float* x    = (const float*)d_in[0];
    const int*   ei   = (const int*)d_in[1];   // int32 (JAX x64 disabled)
    const float* W1   = (const float*)d_in[2];
    const float* as1  = (const float*)d_in[3];
    const float* ad1  = (const float*)d_in[4];
    const float* b1   = (const float*)d_in[5];
    const float* W2   = (const float*)d_in[6];
    const float* as2  = (const float*)d_in[7];
    const float* ad2  = (const float*)d_in[8];
    const float* b2   = (const float*)d_in[9];
    float* out = (float*)d_out;

    void* degp = nullptr;
    cudaGetSymbolAddress(&degp, g_deg);
    cudaMemsetAsync(degp, 0, NN * sizeof(int));

    k_count<<<(EE / 4 + 255) / 256, 256>>>(ei);
    k_scan1<<<(NN + 1023) / 1024, 1024>>>();
    k_scan2<<<1, 64>>>();
    k_scan3<<<(NN + 255) / 256, 256>>>();
    k_scatter<<<(EE / 4 + 255) / 256, 256>>>(ei);

    k_gemm1<<<(NN + 63) / 64, 256>>>(x, W1, as1, ad1);
    k_agg1<<<(NN + 7) / 8, 256>>>(b1);

    k_gemm2<<<(NN + 127) / 128, 256>>>(W2, as2, ad2);
    k_agg2<<<(NN + 7) / 8, 256>>>(b2, out);
}

// round 6
// speedup vs baseline: 2.0041x; 1.1398x over previous
#include <cuda_runtime.h>
#include <cuda_fp16.h>

#define NN 50000
#define EE 800000
#define CIN 64
#define H1 4
#define C1 256   // H1*64
#define NEG 0.2f

// ---------------- device scratch (no runtime allocation allowed) -----------
__device__ __half g_h1b[NN * C1];  // layer1 linear output, fp16 (gather path)
__device__ __half g_h1r[NN * C1];  // relu(aggregated layer1), fp16 = layer2 input
__device__ float g_as1[NN * H1];
__device__ float g_ad1[NN * H1];
__device__ __half g_h2[NN * CIN];  // layer2 linear output, fp16 (gather path)
__device__ float g_as2[NN];
__device__ float g_ad2[NN];
__device__ int   g_deg[NN];
__device__ int   g_offs[NN + 1];
__device__ int   g_cur[NN];
__device__ int   g_csrc[EE];       // CSR-by-dst: src node ids
__device__ int   g_part[64];       // scan block partials

__device__ __forceinline__ int clampN(int v) {
    return v < 0 ? 0 : (v >= NN ? NN - 1 : v);
}

// ---------------- packed f32x2 helpers (Blackwell FFMA2) -------------------
__device__ __forceinline__ unsigned long long pk2(float x, float y) {
    unsigned long long r;
    asm("mov.b64 %0, {%1, %2};" : "=l"(r)
        : "r"(__float_as_uint(x)), "r"(__float_as_uint(y)));
    return r;
}
__device__ __forceinline__ void upk2(unsigned long long v, float &x, float &y) {
    unsigned int lo, hi;
    asm("mov.b64 {%0, %1}, %2;" : "=r"(lo), "=r"(hi) : "l"(v));
    x = __uint_as_float(lo); y = __uint_as_float(hi);
}
__device__ __forceinline__ void fma2(unsigned long long &d,
                                     unsigned long long a,
                                     unsigned long long b) {
    asm("fma.rn.f32x2 %0, %1, %2, %0;" : "+l"(d) : "l"(a), "l"(b));
}

__device__ __forceinline__ float2 h2f2(unsigned u) {
    return __half22float2(*reinterpret_cast<__half2*>(&u));
}

// ---------------- CSR construction ----------------------------------------
__global__ void k_count(const int* __restrict__ ei) {
    int e4 = blockIdx.x * blockDim.x + threadIdx.x;
    if (e4 < EE / 4) {
        int4 d = *(const int4*)(ei + EE + 4 * e4);
        atomicAdd(&g_deg[clampN(d.x)], 1);
        atomicAdd(&g_deg[clampN(d.y)], 1);
        atomicAdd(&g_deg[clampN(d.z)], 1);
        atomicAdd(&g_deg[clampN(d.w)], 1);
    }
}

// 3-stage scan: block-local inclusive -> partial scan -> add-back
__global__ void __launch_bounds__(1024) k_scan1() {
    __shared__ int wsum[32];
    int t = threadIdx.x, b = blockIdx.x;
    int i = b * 1024 + t;
    int lane = t & 31, w = t >> 5;
    int v = (i < NN) ? g_deg[i] : 0;
    int x = v;
#pragma unroll
    for (int off = 1; off < 32; off <<= 1) {
        int u = __shfl_up_sync(0xffffffffu, x, off);
        if (lane >= off) x += u;
    }
    if (lane == 31) wsum[w] = x;
    __syncthreads();
    if (w == 0) {
        int s = wsum[lane];
#pragma unroll
        for (int off = 1; off < 32; off <<= 1) {
            int u = __shfl_up_sync(0xffffffffu, s, off);
            if (lane >= off) s += u;
        }
        wsum[lane] = s;
    }
    __syncthreads();
    int incl = x + (w > 0 ? wsum[w - 1] : 0);
    if (i < NN) g_offs[i + 1] = incl;     // block-local inclusive
    if (t == 1023) g_part[b] = incl;
}

__global__ void k_scan2() {   // 1 block, 64 threads; 49 partials
    __shared__ int sm[64];
    int t = threadIdx.x;
    sm[t] = (t < 49) ? g_part[t] : 0;
    __syncthreads();
#pragma unroll
    for (int off = 1; off < 64; off <<= 1) {
        int u = (t >= off) ? sm[t - off] : 0;
        __syncthreads();
        sm[t] += u;
        __syncthreads();
    }
    if (t < 49) g_part[t] = t ? sm[t - 1] : 0;   // exclusive
}

__global__ void k_scan3() {
    int i = blockIdx.x * blockDim.x + threadIdx.x;
    if (i == 0) g_offs[0] = 0;
    if (i < NN) {
        int v = g_offs[i + 1] + g_part[i >> 10];
        g_offs[i + 1] = v;
        g_cur[i] = v - g_deg[i];
    }
}

__global__ void k_scatter(const int* __restrict__ ei) {
    int e4 = blockIdx.x * blockDim.x + threadIdx.x;
    if (e4 < EE / 4) {
        int4 s = *(const int4*)(ei + 4 * e4);
        int4 d = *(const int4*)(ei + EE + 4 * e4);
        int p0 = atomicAdd(&g_cur[clampN(d.x)], 1);
        int p1 = atomicAdd(&g_cur[clampN(d.y)], 1);
        int p2 = atomicAdd(&g_cur[clampN(d.z)], 1);
        int p3 = atomicAdd(&g_cur[clampN(d.w)], 1);
        g_csrc[p0] = clampN(s.x);
        g_csrc[p1] = clampN(s.y);
        g_csrc[p2] = clampN(s.z);
        g_csrc[p3] = clampN(s.w);
    }
}

// ---------------- GEMM 1: h1 = x[N,64] @ W1[64,256] ------------------------
__global__ void __launch_bounds__(256) k_gemm1(const float* __restrict__ x,
                                               const float* __restrict__ W1,
                                               const float* __restrict__ att_s,
                                               const float* __restrict__ att_d) {
    __shared__ float sx[64 * 32];    // [row][kchunk]  8KB
    __shared__ float sW[32 * 256];   // [k][col]      32KB
    int t = threadIdx.x;
    int row0 = blockIdx.x * 64;
    int cg = t & 31, rg = t >> 5;
    unsigned long long acc[8][4];
#pragma unroll
    for (int m = 0; m < 8; m++)
#pragma unroll
        for (int c = 0; c < 4; c++) acc[m][c] = 0ull;

    for (int kc = 0; kc < 2; kc++) {
        __syncthreads();
        {
            float4* s4 = (float4*)sx;
#pragma unroll
            for (int q = 0; q < 2; q++) {
                int idx = t + q * 256;           // 0..511
                int row = idx >> 3, j = idx & 7;
                float4 v = make_float4(0.f, 0.f, 0.f, 0.f);
                if (row0 + row < NN)
                    v = *(const float4*)(x + (size_t)(row0 + row) * 64 + kc * 32 + j * 4);
                s4[idx] = v;
            }
            float4* w4 = (float4*)sW;
            const float4* wg = (const float4*)(W1 + kc * 32 * 256);
#pragma unroll
            for (int q = 0; q < 8; q++) w4[t + q * 256] = wg[t + q * 256];
        }
        __syncthreads();
        const float* xrow = sx + rg * 8 * 32;
#pragma unroll 2
        for (int k4 = 0; k4 < 8; k4++) {
            float4 xq[8];
#pragma unroll
            for (int m = 0; m < 8; m++)
                xq[m] = *(const float4*)(xrow + m * 32 + k4 * 4);
#pragma unroll
            for (int j = 0; j < 4; j++) {
                const ulonglong2* wp =
                    (const ulonglong2*)(sW + (k4 * 4 + j) * 256 + cg * 8);
                ulonglong2 wa = wp[0];
                ulonglong2 wb = wp[1];
#pragma unroll
                for (int m = 0; m < 8; m++) {
                    float xs = (j == 0) ? xq[m].x : (j == 1) ? xq[m].y
                             : (j == 2) ? xq[m].z : xq[m].w;
                    unsigned long long xd = pk2(xs, xs);
                    fma2(acc[m][0], xd, wa.x);
                    fma2(acc[m][1], xd, wa.y);
                    fma2(acc[m][2], xd, wb.x);
                    fma2(acc[m][3], xd, wb.y);
                }
            }
        }
    }
    // epilogue: fp16 store + fused attention scalar reduction
    int cb = cg * 8;
    float asv[8], adv[8];
#pragma unroll
    for (int q = 0; q < 8; q++) { asv[q] = att_s[cb + q]; adv[q] = att_d[cb + q]; }
#pragma unroll
    for (int m = 0; m < 8; m++) {
        int row = row0 + rg * 8 + m;
        float v[8];
        upk2(acc[m][0], v[0], v[1]);
        upk2(acc[m][1], v[2], v[3]);
        upk2(acc[m][2], v[4], v[5]);
        upk2(acc[m][3], v[6], v[7]);
        float ps = 0.f, pd = 0.f;
#pragma unroll
        for (int q = 0; q < 8; q++) { ps += v[q] * asv[q]; pd += v[q] * adv[q]; }
#pragma unroll
        for (int off = 4; off; off >>= 1) {
            ps += __shfl_xor_sync(0xffffffffu, ps, off);
            pd += __shfl_xor_sync(0xffffffffu, pd, off);
        }
        if (row < NN) {
            __half2 p0 = __floats2half2_rn(v[0], v[1]);
            __half2 p1 = __floats2half2_rn(v[2], v[3]);
            __half2 p2 = __floats2half2_rn(v[4], v[5]);
            __half2 p3 = __floats2half2_rn(v[6], v[7]);
            uint4 u;
            u.x = *reinterpret_cast<unsigned*>(&p0);
            u.y = *reinterpret_cast<unsigned*>(&p1);
            u.z = *reinterpret_cast<unsigned*>(&p2);
            u.w = *reinterpret_cast<unsigned*>(&p3);
            *(uint4*)(g_h1b + (size_t)row * C1 + cb) = u;
            if ((cg & 7) == 0) {
                int h = cg >> 3;
                g_as1[row * H1 + h] = ps;
                g_ad1[row * H1 + h] = pd;
            }
        }
    }
}

// ---------------- GEMM 2: h2 = h1r[N,256] @ W2[256,64] ---------------------
__global__ void __launch_bounds__(256) k_gemm2(const float* __restrict__ W2,
                                               const float* __restrict__ att_s,
                                               const float* __restrict__ att_d) {
    __shared__ float sx[128 * 32];   // 16KB
    __shared__ float sW[32 * 64];    //  8KB
    int t = threadIdx.x;
    int row0 = blockIdx.x * 128;
    int cg = t & 15, rg = t >> 4;
    unsigned long long acc[8][2];
#pragma unroll
    for (int m = 0; m < 8; m++) { acc[m][0] = 0ull; acc[m][1] = 0ull; }

    for (int kc = 0; kc < 8; kc++) {
        __syncthreads();
        {
            float4* s4 = (float4*)sx;
#pragma unroll
            for (int q = 0; q < 4; q++) {
                int idx = t + q * 256;           // 0..1023
                int row = idx >> 3, j = idx & 7;
                float4 v = make_float4(0.f, 0.f, 0.f, 0.f);
                if (row0 + row < NN) {
                    uint2 hv = *(const uint2*)(g_h1r + (size_t)(row0 + row) * C1 + kc * 32 + j * 4);
                    float2 f0 = h2f2(hv.x);
                    float2 f1 = h2f2(hv.y);
                    v = make_float4(f0.x, f0.y, f1.x, f1.y);
                }
                s4[idx] = v;
            }
            float4* w4 = (float4*)sW;
            const float4* wg = (const float4*)(W2 + kc * 32 * 64);
#pragma unroll
            for (int q = 0; q < 2; q++) w4[t + q * 256] = wg[t + q * 256];
        }
        __syncthreads();
        const float* xrow = sx + rg * 8 * 32;
#pragma unroll 2
        for (int k4 = 0; k4 < 8; k4++) {
            float4 xq[8];
#pragma unroll
            for (int m = 0; m < 8; m++)
                xq[m] = *(const float4*)(xrow + m * 32 + k4 * 4);
#pragma unroll
            for (int j = 0; j < 4; j++) {
                ulonglong2 wv =
                    *(const ulonglong2*)(sW + (k4 * 4 + j) * 64 + cg * 4);
#pragma unroll
                for (int m = 0; m < 8; m++) {
                    float xs = (j == 0) ? xq[m].x : (j == 1) ? xq[m].y
                             : (j == 2) ? xq[m].z : xq[m].w;
                    unsigned long long xd = pk2(xs, xs);
                    fma2(acc[m][0], xd, wv.x);
                    fma2(acc[m][1], xd, wv.y);
                }
            }
        }
    }
    int cb = cg * 4;
    float asv[4], adv[4];
#pragma unroll
    for (int q = 0; q < 4; q++) { asv[q] = att_s[cb + q]; adv[q] = att_d[cb + q]; }
#pragma unroll
    for (int m = 0; m < 8; m++) {
        int row = row0 + rg * 8 + m;
        float v[4];
        upk2(acc[m][0], v[0], v[1]);
        upk2(acc[m][1], v[2], v[3]);
        float ps = 0.f, pd = 0.f;
#pragma unroll
        for (int q = 0; q < 4; q++) { ps += v[q] * asv[q]; pd += v[q] * adv[q]; }
#pragma unroll
        for (int off = 8; off; off >>= 1) {
            ps += __shfl_xor_sync(0xffffffffu, ps, off);
            pd += __shfl_xor_sync(0xffffffffu, pd, off);
        }
        if (row < NN) {
            __half2 p0 = __floats2half2_rn(v[0], v[1]);
            __half2 p1 = __floats2half2_rn(v[2], v[3]);
            uint2 u;
            u.x = *reinterpret_cast<unsigned*>(&p0);
            u.y = *reinterpret_cast<unsigned*>(&p1);
            *(uint2*)(g_h2 + (size_t)row * CIN + cb) = u;
            if (cg == 0) { g_as2[row] = ps; g_ad2[row] = pd; }
        }
    }
}

__device__ __forceinline__ float lrelu(float x) {
    return x > 0.f ? x : NEG * x;
}

// ---------------- layer-1 aggregation: warp per dst node -------------------
// Softmax without max-subtraction (logit std ~1.4; exp range safe in fp32).
__global__ void __launch_bounds__(256) k_agg1(const float* __restrict__ b1) {
    int wid = (blockIdx.x * blockDim.x + threadIdx.x) >> 5;
    int lane = threadIdx.x & 31;
    if (wid >= NN) return;
    int beg = g_offs[wid], end = g_offs[wid + 1];
    int c0 = lane * 8;
    __half* outp = g_h1r + (size_t)wid * C1 + c0;
    float bb[8];
#pragma unroll
    for (int q = 0; q < 8; q++) bb[q] = b1[c0 + q];
    if (beg == end) {
        __half2 p0 = __floats2half2_rn(fmaxf(bb[0], 0.f), fmaxf(bb[1], 0.f));
        __half2 p1 = __floats2half2_rn(fmaxf(bb[2], 0.f), fmaxf(bb[3], 0.f));
        __half2 p2 = __floats2half2_rn(fmaxf(bb[4], 0.f), fmaxf(bb[5], 0.f));
        __half2 p3 = __floats2half2_rn(fmaxf(bb[6], 0.f), fmaxf(bb[7], 0.f));
        uint4 u;
        u.x = *reinterpret_cast<unsigned*>(&p0);
        u.y = *reinterpret_cast<unsigned*>(&p1);
        u.z = *reinterpret_cast<unsigned*>(&p2);
        u.w = *reinterpret_cast<unsigned*>(&p3);
        *(uint4*)outp = u;
        return;
    }
    float4 ad4 = *(const float4*)(g_ad1 + (size_t)wid * H1);
    float ad[4] = {ad4.x, ad4.y, ad4.z, ad4.w};
    float sum[4] = {0.f, 0.f, 0.f, 0.f};
    // pass 1: plain sum of exp
    for (int i = beg + lane; i < end; i += 32) {
        int s = g_csrc[i];
        float4 as4 = *(const float4*)(g_as1 + (size_t)s * H1);
        sum[0] += __expf(lrelu(as4.x + ad[0]));
        sum[1] += __expf(lrelu(as4.y + ad[1]));
        sum[2] += __expf(lrelu(as4.z + ad[2]));
        sum[3] += __expf(lrelu(as4.w + ad[3]));
    }
#pragma unroll
    for (int off = 16; off; off >>= 1) {
#pragma unroll
        for (int h = 0; h < 4; h++)
            sum[h] += __shfl_xor_sync(0xffffffffu, sum[h], off);
    }
    int head = lane >> 3;
    float invh = 1.f / sum[head];
    float adh = ad[head];
    float acc[8];
#pragma unroll
    for (int q = 0; q < 8; q++) acc[q] = 0.f;
    int i = beg;
    // 4-way unrolled fp16 gather
    for (; i + 4 <= end; i += 4) {
        int s0 = g_csrc[i], s1 = g_csrc[i + 1], s2 = g_csrc[i + 2], s3 = g_csrc[i + 3];
        float A0 = g_as1[s0 * H1 + head];
        float A1 = g_as1[s1 * H1 + head];
        float A2 = g_as1[s2 * H1 + head];
        float A3 = g_as1[s3 * H1 + head];
        uint4 u0 = *(const uint4*)(g_h1b + (size_t)s0 * C1 + c0);
        uint4 u1 = *(const uint4*)(g_h1b + (size_t)s1 * C1 + c0);
        uint4 u2 = *(const uint4*)(g_h1b + (size_t)s2 * C1 + c0);
        uint4 u3 = *(const uint4*)(g_h1b + (size_t)s3 * C1 + c0);
        float w0 = __expf(lrelu(A0 + adh)) * invh;
        float w1 = __expf(lrelu(A1 + adh)) * invh;
        float w2 = __expf(lrelu(A2 + adh)) * invh;
        float w3 = __expf(lrelu(A3 + adh)) * invh;
#pragma unroll
        for (int q = 0; q < 4; q++) {
            float2 f0 = h2f2((&u0.x)[q]);
            float2 f1 = h2f2((&u1.x)[q]);
            float2 f2 = h2f2((&u2.x)[q]);
            float2 f3 = h2f2((&u3.x)[q]);
            acc[2 * q]     += w0 * f0.x + w1 * f1.x + w2 * f2.x + w3 * f3.x;
            acc[2 * q + 1] += w0 * f0.y + w1 * f1.y + w2 * f2.y + w3 * f3.y;
        }
    }
    for (; i < end; i++) {
        int s = g_csrc[i];
        float asv = g_as1[s * H1 + head];
        float wgt = __expf(lrelu(asv + adh)) * invh;
        uint4 u = *(const uint4*)(g_h1b + (size_t)s * C1 + c0);
#pragma unroll
        for (int q = 0; q < 4; q++) {
            float2 f = h2f2((&u.x)[q]);
            acc[2 * q]     += wgt * f.x;
            acc[2 * q + 1] += wgt * f.y;
        }
    }
    __half2 p0 = __floats2half2_rn(fmaxf(acc[0] + bb[0], 0.f), fmaxf(acc[1] + bb[1], 0.f));
    __half2 p1 = __floats2half2_rn(fmaxf(acc[2] + bb[2], 0.f), fmaxf(acc[3] + bb[3], 0.f));
    __half2 p2 = __floats2half2_rn(fmaxf(acc[4] + bb[4], 0.f), fmaxf(acc[5] + bb[5], 0.f));
    __half2 p3 = __floats2half2_rn(fmaxf(acc[6] + bb[6], 0.f), fmaxf(acc[7] + bb[7], 0.f));
    uint4 u;
    u.x = *reinterpret_cast<unsigned*>(&p0);
    u.y = *reinterpret_cast<unsigned*>(&p1);
    u.z = *reinterpret_cast<unsigned*>(&p2);
    u.w = *reinterpret_cast<unsigned*>(&p3);
    *(uint4*)outp = u;
}

// ---------------- layer-2 aggregation: warp per dst node -------------------
__global__ void __launch_bounds__(256) k_agg2(const float* __restrict__ b2,
                                              float* __restrict__ out) {
    int wid = (blockIdx.x * blockDim.x + threadIdx.x) >> 5;
    int lane = threadIdx.x & 31;
    if (wid >= NN) return;
    int beg = g_offs[wid], end = g_offs[wid + 1];
    int c0 = lane * 2;
    float* outp = out + (size_t)wid * CIN + c0;
    float b0 = b2[c0], b1v = b2[c0 + 1];
    if (beg == end) {
        outp[0] = b0;
        outp[1] = b1v;
        return;
    }
    float ad = g_ad2[wid];
    float sum = 0.f;
    for (int i = beg + lane; i < end; i += 32)
        sum += __expf(lrelu(g_as2[g_csrc[i]] + ad));
#pragma unroll
    for (int off = 16; off; off >>= 1)
        sum += __shfl_xor_sync(0xffffffffu, sum, off);
    float inv = 1.f / sum;
    float acc0 = 0.f, acc1 = 0.f;
    int i = beg;
    for (; i + 4 <= end; i += 4) {
        int s0 = g_csrc[i], s1 = g_csrc[i + 1], s2 = g_csrc[i + 2], s3 = g_csrc[i + 3];
        float e0 = g_as2[s0], e1 = g_as2[s1], e2 = g_as2[s2], e3 = g_as2[s3];
        unsigned u0 = *(const unsigned*)(g_h2 + (size_t)s0 * CIN + c0);
        unsigned u1 = *(const unsigned*)(g_h2 + (size_t)s1 * CIN + c0);
        unsigned u2 = *(const unsigned*)(g_h2 + (size_t)s2 * CIN + c0);
        unsigned u3 = *(const unsigned*)(g_h2 + (size_t)s3 * CIN + c0);
        float w0 = __expf(lrelu(e0 + ad)) * inv;
        float w1 = __expf(lrelu(e1 + ad)) * inv;
        float w2 = __expf(lrelu(e2 + ad)) * inv;
        float w3 = __expf(lrelu(e3 + ad)) * inv;
        float2 v0 = h2f2(u0), v1 = h2f2(u1), v2 = h2f2(u2), v3 = h2f2(u3);
        acc0 += w0 * v0.x + w1 * v1.x + w2 * v2.x + w3 * v3.x;
        acc1 += w0 * v0.y + w1 * v1.y + w2 * v2.y + w3 * v3.y;
    }
    for (; i < end; i++) {
        int s = g_csrc[i];
        float wgt = __expf(lrelu(g_as2[s] + ad)) * inv;
        float2 v = h2f2(*(const unsigned*)(g_h2 + (size_t)s * CIN + c0));
        acc0 += wgt * v.x;
        acc1 += wgt * v.y;
    }
    outp[0] = acc0 + b0;
    outp[1] = acc1 + b1v;
}

// ---------------- launcher -------------------------------------------------
// CSR build (default stream) runs concurrently with gemm1 (side stream);
// event fork/join keeps it graph-capturable.
extern "C" void kernel_launch(void* const* d_in, const int* in_sizes, int n_in,
                              void* d_out, int out_size) {
    const float* x    = (const float*)d_in[0];
    const int*   ei   = (const int*)d_in[1];   // int32 (JAX x64 disabled)
    const float* W1   = (const float*)d_in[2];
    const float* as1  = (const float*)d_in[3];
    const float* ad1  = (const float*)d_in[4];
    const float* b1   = (const float*)d_in[5];
    const float* W2   = (const float*)d_in[6];
    const float* as2  = (const float*)d_in[7];
    const float* ad2  = (const float*)d_in[8];
    const float* b2   = (const float*)d_in[9];
    float* out = (float*)d_out;

    cudaStream_t side;
    cudaEvent_t ev_fork, ev_join;
    cudaStreamCreateWithFlags(&side, cudaStreamNonBlocking);
    cudaEventCreateWithFlags(&ev_fork, cudaEventDisableTiming);
    cudaEventCreateWithFlags(&ev_join, cudaEventDisableTiming);

    // fork: gemm1 on side stream (independent of CSR build)
    cudaEventRecord(ev_fork, 0);
    cudaStreamWaitEvent(side, ev_fork, 0);
    k_gemm1<<<(NN + 63) / 64, 256, 0, side>>>(x, W1, as1, ad1);
    cudaEventRecord(ev_join, side);

    // CSR build on default stream
    void* degp = nullptr;
    cudaGetSymbolAddress(&degp, g_deg);
    cudaMemsetAsync(degp, 0, NN * sizeof(int));
    k_count<<<(EE / 4 + 255) / 256, 256>>>(ei);
    k_scan1<<<(NN + 1023) / 1024, 1024>>>();
    k_scan2<<<1, 64>>>();
    k_scan3<<<(NN + 255) / 256, 256>>>();
    k_scatter<<<(EE / 4 + 255) / 256, 256>>>(ei);

    // join: agg1 needs both gemm1 and CSR
    cudaStreamWaitEvent(0, ev_join, 0);
    k_agg1<<<(NN + 7) / 8, 256>>>(b1);

    k_gemm2<<<(NN + 127) / 128, 256>>>(W2, as2, ad2);
    k_agg2<<<(NN + 7) / 8, 256>>>(b2, out);

    // host-side cleanup (no device ops)
    cudaEventDestroy(ev_fork);
    cudaEventDestroy(ev_join);
    cudaStreamDestroy(side);
}

// round 7
// speedup vs baseline: 2.0699x; 1.0328x over previous
#include <cuda_runtime.h>
#include <cuda_fp16.h>

#define NN 50000
#define EE 800000
#define CIN 64
#define H1 4
#define C1 256   // H1*64
#define NEG 0.2f

// ---------------- device scratch (no runtime allocation allowed) -----------
__device__ __half g_h1b[NN * C1];  // layer1 linear output, fp16 (gather path)
__device__ __half g_h1r[NN * C1];  // relu(aggregated layer1), fp16 = layer2 input
__device__ float g_as1[NN * H1];
__device__ float g_ad1[NN * H1];
__device__ __half g_h2[NN * CIN];  // layer2 linear output, fp16 (gather path)
__device__ float g_as2[NN];
__device__ float g_ad2[NN];
__device__ int   g_deg[NN];
__device__ int   g_offs[NN + 1];
__device__ int   g_cur[NN];
__device__ int   g_csrc[EE];       // CSR-by-dst: src node ids
__device__ int   g_part[64];       // scan block partials

__device__ __forceinline__ int clampN(int v) {
    return v < 0 ? 0 : (v >= NN ? NN - 1 : v);
}

// ---------------- packed f32x2 helpers (Blackwell FFMA2) -------------------
__device__ __forceinline__ unsigned long long pk2(float x, float y) {
    unsigned long long r;
    asm("mov.b64 %0, {%1, %2};" : "=l"(r)
        : "r"(__float_as_uint(x)), "r"(__float_as_uint(y)));
    return r;
}
__device__ __forceinline__ void upk2(unsigned long long v, float &x, float &y) {
    unsigned int lo, hi;
    asm("mov.b64 {%0, %1}, %2;" : "=r"(lo), "=r"(hi) : "l"(v));
    x = __uint_as_float(lo); y = __uint_as_float(hi);
}
__device__ __forceinline__ void fma2(unsigned long long &d,
                                     unsigned long long a,
                                     unsigned long long b) {
    asm("fma.rn.f32x2 %0, %1, %2, %0;" : "+l"(d) : "l"(a), "l"(b));
}

__device__ __forceinline__ float2 h2f2(unsigned u) {
    return __half22float2(*reinterpret_cast<__half2*>(&u));
}

// ---------------- CSR construction ----------------------------------------
__global__ void k_count(const int* __restrict__ ei) {
    int e4 = blockIdx.x * blockDim.x + threadIdx.x;
    if (e4 < EE / 4) {
        int4 d = *(const int4*)(ei + EE + 4 * e4);
        atomicAdd(&g_deg[clampN(d.x)], 1);
        atomicAdd(&g_deg[clampN(d.y)], 1);
        atomicAdd(&g_deg[clampN(d.z)], 1);
        atomicAdd(&g_deg[clampN(d.w)], 1);
    }
}

// 3-stage scan: block-local inclusive -> partial scan -> add-back
__global__ void __launch_bounds__(1024) k_scan1() {
    __shared__ int wsum[32];
    int t = threadIdx.x, b = blockIdx.x;
    int i = b * 1024 + t;
    int lane = t & 31, w = t >> 5;
    int v = (i < NN) ? g_deg[i] : 0;
    int x = v;
#pragma unroll
    for (int off = 1; off < 32; off <<= 1) {
        int u = __shfl_up_sync(0xffffffffu, x, off);
        if (lane >= off) x += u;
    }
    if (lane == 31) wsum[w] = x;
    __syncthreads();
    if (w == 0) {
        int s = wsum[lane];
#pragma unroll
        for (int off = 1; off < 32; off <<= 1) {
            int u = __shfl_up_sync(0xffffffffu, s, off);
            if (lane >= off) s += u;
        }
        wsum[lane] = s;
    }
    __syncthreads();
    int incl = x + (w > 0 ? wsum[w - 1] : 0);
    if (i < NN) g_offs[i + 1] = incl;     // block-local inclusive
    if (t == 1023) g_part[b] = incl;
}

__global__ void k_scan2() {   // 1 block, 64 threads; 49 partials
    __shared__ int sm[64];
    int t = threadIdx.x;
    sm[t] = (t < 49) ? g_part[t] : 0;
    __syncthreads();
#pragma unroll
    for (int off = 1; off < 64; off <<= 1) {
        int u = (t >= off) ? sm[t - off] : 0;
        __syncthreads();
        sm[t] += u;
        __syncthreads();
    }
    if (t < 49) g_part[t] = t ? sm[t - 1] : 0;   // exclusive
}

__global__ void k_scan3() {
    int i = blockIdx.x * blockDim.x + threadIdx.x;
    if (i == 0) g_offs[0] = 0;
    if (i < NN) {
        int v = g_offs[i + 1] + g_part[i >> 10];
        g_offs[i + 1] = v;
        g_cur[i] = v - g_deg[i];
    }
}

__global__ void k_scatter(const int* __restrict__ ei) {
    int e4 = blockIdx.x * blockDim.x + threadIdx.x;
    if (e4 < EE / 4) {
        int4 s = *(const int4*)(ei + 4 * e4);
        int4 d = *(const int4*)(ei + EE + 4 * e4);
        int p0 = atomicAdd(&g_cur[clampN(d.x)], 1);
        int p1 = atomicAdd(&g_cur[clampN(d.y)], 1);
        int p2 = atomicAdd(&g_cur[clampN(d.z)], 1);
        int p3 = atomicAdd(&g_cur[clampN(d.w)], 1);
        g_csrc[p0] = clampN(s.x);
        g_csrc[p1] = clampN(s.y);
        g_csrc[p2] = clampN(s.z);
        g_csrc[p3] = clampN(s.w);
    }
}

// ---------------- GEMM 1: h1 = x[N,64] @ W1[64,256] ------------------------
__global__ void __launch_bounds__(256) k_gemm1(const float* __restrict__ x,
                                               const float* __restrict__ W1,
                                               const float* __restrict__ att_s,
                                               const float* __restrict__ att_d) {
    __shared__ float sx[64 * 32];    // [row][kchunk]  8KB
    __shared__ float sW[32 * 256];   // [k][col]      32KB
    int t = threadIdx.x;
    int row0 = blockIdx.x * 64;
    int cg = t & 31, rg = t >> 5;
    unsigned long long acc[8][4];
#pragma unroll
    for (int m = 0; m < 8; m++)
#pragma unroll
        for (int c = 0; c < 4; c++) acc[m][c] = 0ull;

    for (int kc = 0; kc < 2; kc++) {
        __syncthreads();
        {
            float4* s4 = (float4*)sx;
#pragma unroll
            for (int q = 0; q < 2; q++) {
                int idx = t + q * 256;           // 0..511
                int row = idx >> 3, j = idx & 7;
                float4 v = make_float4(0.f, 0.f, 0.f, 0.f);
                if (row0 + row < NN)
                    v = *(const float4*)(x + (size_t)(row0 + row) * 64 + kc * 32 + j * 4);
                s4[idx] = v;
            }
            float4* w4 = (float4*)sW;
            const float4* wg = (const float4*)(W1 + kc * 32 * 256);
#pragma unroll
            for (int q = 0; q < 8; q++) w4[t + q * 256] = wg[t + q * 256];
        }
        __syncthreads();
        const float* xrow = sx + rg * 8 * 32;
#pragma unroll 2
        for (int k4 = 0; k4 < 8; k4++) {
            float4 xq[8];
#pragma unroll
            for (int m = 0; m < 8; m++)
                xq[m] = *(const float4*)(xrow + m * 32 + k4 * 4);
#pragma unroll
            for (int j = 0; j < 4; j++) {
                const ulonglong2* wp =
                    (const ulonglong2*)(sW + (k4 * 4 + j) * 256 + cg * 8);
                ulonglong2 wa = wp[0];
                ulonglong2 wb = wp[1];
#pragma unroll
                for (int m = 0; m < 8; m++) {
                    float xs = (j == 0) ? xq[m].x : (j == 1) ? xq[m].y
                             : (j == 2) ? xq[m].z : xq[m].w;
                    unsigned long long xd = pk2(xs, xs);
                    fma2(acc[m][0], xd, wa.x);
                    fma2(acc[m][1], xd, wa.y);
                    fma2(acc[m][2], xd, wb.x);
                    fma2(acc[m][3], xd, wb.y);
                }
            }
        }
    }
    // epilogue: fp16 store + fused attention scalar reduction
    int cb = cg * 8;
    float asv[8], adv[8];
#pragma unroll
    for (int q = 0; q < 8; q++) { asv[q] = att_s[cb + q]; adv[q] = att_d[cb + q]; }
#pragma unroll
    for (int m = 0; m < 8; m++) {
        int row = row0 + rg * 8 + m;
        float v[8];
        upk2(acc[m][0], v[0], v[1]);
        upk2(acc[m][1], v[2], v[3]);
        upk2(acc[m][2], v[4], v[5]);
        upk2(acc[m][3], v[6], v[7]);
        float ps = 0.f, pd = 0.f;
#pragma unroll
        for (int q = 0; q < 8; q++) { ps += v[q] * asv[q]; pd += v[q] * adv[q]; }
#pragma unroll
        for (int off = 4; off; off >>= 1) {
            ps += __shfl_xor_sync(0xffffffffu, ps, off);
            pd += __shfl_xor_sync(0xffffffffu, pd, off);
        }
        if (row < NN) {
            __half2 p0 = __floats2half2_rn(v[0], v[1]);
            __half2 p1 = __floats2half2_rn(v[2], v[3]);
            __half2 p2 = __floats2half2_rn(v[4], v[5]);
            __half2 p3 = __floats2half2_rn(v[6], v[7]);
            uint4 u;
            u.x = *reinterpret_cast<unsigned*>(&p0);
            u.y = *reinterpret_cast<unsigned*>(&p1);
            u.z = *reinterpret_cast<unsigned*>(&p2);
            u.w = *reinterpret_cast<unsigned*>(&p3);
            *(uint4*)(g_h1b + (size_t)row * C1 + cb) = u;
            if ((cg & 7) == 0) {
                int h = cg >> 3;
                g_as1[row * H1 + h] = ps;
                g_ad1[row * H1 + h] = pd;
            }
        }
    }
}

// ---------------- GEMM 2: h2 = h1r[N,256] @ W2[256,64] ---------------------
__global__ void __launch_bounds__(256) k_gemm2(const float* __restrict__ W2,
                                               const float* __restrict__ att_s,
                                               const float* __restrict__ att_d) {
    __shared__ float sx[128 * 32];   // 16KB
    __shared__ float sW[32 * 64];    //  8KB
    int t = threadIdx.x;
    int row0 = blockIdx.x * 128;
    int cg = t & 15, rg = t >> 4;
    unsigned long long acc[8][2];
#pragma unroll
    for (int m = 0; m < 8; m++) { acc[m][0] = 0ull; acc[m][1] = 0ull; }

    for (int kc = 0; kc < 8; kc++) {
        __syncthreads();
        {
            float4* s4 = (float4*)sx;
#pragma unroll
            for (int q = 0; q < 4; q++) {
                int idx = t + q * 256;           // 0..1023
                int row = idx >> 3, j = idx & 7;
                float4 v = make_float4(0.f, 0.f, 0.f, 0.f);
                if (row0 + row < NN) {
                    uint2 hv = *(const uint2*)(g_h1r + (size_t)(row0 + row) * C1 + kc * 32 + j * 4);
                    float2 f0 = h2f2(hv.x);
                    float2 f1 = h2f2(hv.y);
                    v = make_float4(f0.x, f0.y, f1.x, f1.y);
                }
                s4[idx] = v;
            }
            float4* w4 = (float4*)sW;
            const float4* wg = (const float4*)(W2 + kc * 32 * 64);
#pragma unroll
            for (int q = 0; q < 2; q++) w4[t + q * 256] = wg[t + q * 256];
        }
        __syncthreads();
        const float* xrow = sx + rg * 8 * 32;
#pragma unroll 2
        for (int k4 = 0; k4 < 8; k4++) {
            float4 xq[8];
#pragma unroll
            for (int m = 0; m < 8; m++)
                xq[m] = *(const float4*)(xrow + m * 32 + k4 * 4);
#pragma unroll
            for (int j = 0; j < 4; j++) {
                ulonglong2 wv =
                    *(const ulonglong2*)(sW + (k4 * 4 + j) * 64 + cg * 4);
#pragma unroll
                for (int m = 0; m < 8; m++) {
                    float xs = (j == 0) ? xq[m].x : (j == 1) ? xq[m].y
                             : (j == 2) ? xq[m].z : xq[m].w;
                    unsigned long long xd = pk2(xs, xs);
                    fma2(acc[m][0], xd, wv.x);
                    fma2(acc[m][1], xd, wv.y);
                }
            }
        }
    }
    int cb = cg * 4;
    float asv[4], adv[4];
#pragma unroll
    for (int q = 0; q < 4; q++) { asv[q] = att_s[cb + q]; adv[q] = att_d[cb + q]; }
#pragma unroll
    for (int m = 0; m < 8; m++) {
        int row = row0 + rg * 8 + m;
        float v[4];
        upk2(acc[m][0], v[0], v[1]);
        upk2(acc[m][1], v[2], v[3]);
        float ps = 0.f, pd = 0.f;
#pragma unroll
        for (int q = 0; q < 4; q++) { ps += v[q] * asv[q]; pd += v[q] * adv[q]; }
#pragma unroll
        for (int off = 8; off; off >>= 1) {
            ps += __shfl_xor_sync(0xffffffffu, ps, off);
            pd += __shfl_xor_sync(0xffffffffu, pd, off);
        }
        if (row < NN) {
            __half2 p0 = __floats2half2_rn(v[0], v[1]);
            __half2 p1 = __floats2half2_rn(v[2], v[3]);
            uint2 u;
            u.x = *reinterpret_cast<unsigned*>(&p0);
            u.y = *reinterpret_cast<unsigned*>(&p1);
            *(uint2*)(g_h2 + (size_t)row * CIN + cb) = u;
            if (cg == 0) { g_as2[row] = ps; g_ad2[row] = pd; }
        }
    }
}

__device__ __forceinline__ float lrelu(float x) {
    return x > 0.f ? x : NEG * x;
}

// ---------------- layer-1 aggregation: warp per dst, SINGLE PASS -----------
// out = (Σ w_i v_i) / (Σ w_i), w = exp(lrelu(as+ad)); no max-shift needed.
__global__ void __launch_bounds__(256) k_agg1(const float* __restrict__ b1) {
    int wid = (blockIdx.x * blockDim.x + threadIdx.x) >> 5;
    int lane = threadIdx.x & 31;
    if (wid >= NN) return;
    int beg = g_offs[wid], end = g_offs[wid + 1];
    int c0 = lane * 8;
    __half* outp = g_h1r + (size_t)wid * C1 + c0;
    float bb[8];
#pragma unroll
    for (int q = 0; q < 8; q++) bb[q] = b1[c0 + q];
    if (beg == end) {
        __half2 p0 = __floats2half2_rn(fmaxf(bb[0], 0.f), fmaxf(bb[1], 0.f));
        __half2 p1 = __floats2half2_rn(fmaxf(bb[2], 0.f), fmaxf(bb[3], 0.f));
        __half2 p2 = __floats2half2_rn(fmaxf(bb[4], 0.f), fmaxf(bb[5], 0.f));
        __half2 p3 = __floats2half2_rn(fmaxf(bb[6], 0.f), fmaxf(bb[7], 0.f));
        uint4 u;
        u.x = *reinterpret_cast<unsigned*>(&p0);
        u.y = *reinterpret_cast<unsigned*>(&p1);
        u.z = *reinterpret_cast<unsigned*>(&p2);
        u.w = *reinterpret_cast<unsigned*>(&p3);
        *(uint4*)outp = u;
        return;
    }
    int head = lane >> 3;
    float adh = g_ad1[wid * H1 + head];
    float sum = 0.f;
    float acc[8];
#pragma unroll
    for (int q = 0; q < 8; q++) acc[q] = 0.f;
    int i = beg;
    for (; i + 4 <= end; i += 4) {
        int s0 = g_csrc[i], s1 = g_csrc[i + 1], s2 = g_csrc[i + 2], s3 = g_csrc[i + 3];
        float A0 = g_as1[s0 * H1 + head];
        float A1 = g_as1[s1 * H1 + head];
        float A2 = g_as1[s2 * H1 + head];
        float A3 = g_as1[s3 * H1 + head];
        uint4 u0 = *(const uint4*)(g_h1b + (size_t)s0 * C1 + c0);
        uint4 u1 = *(const uint4*)(g_h1b + (size_t)s1 * C1 + c0);
        uint4 u2 = *(const uint4*)(g_h1b + (size_t)s2 * C1 + c0);
        uint4 u3 = *(const uint4*)(g_h1b + (size_t)s3 * C1 + c0);
        float w0 = __expf(lrelu(A0 + adh));
        float w1 = __expf(lrelu(A1 + adh));
        float w2 = __expf(lrelu(A2 + adh));
        float w3 = __expf(lrelu(A3 + adh));
        sum += (w0 + w1) + (w2 + w3);
#pragma unroll
        for (int q = 0; q < 4; q++) {
            float2 f0 = h2f2((&u0.x)[q]);
            float2 f1 = h2f2((&u1.x)[q]);
            float2 f2 = h2f2((&u2.x)[q]);
            float2 f3 = h2f2((&u3.x)[q]);
            acc[2 * q]     += w0 * f0.x + w1 * f1.x + w2 * f2.x + w3 * f3.x;
            acc[2 * q + 1] += w0 * f0.y + w1 * f1.y + w2 * f2.y + w3 * f3.y;
        }
    }
    for (; i < end; i++) {
        int s = g_csrc[i];
        float wgt = __expf(lrelu(g_as1[s * H1 + head] + adh));
        sum += wgt;
        uint4 u = *(const uint4*)(g_h1b + (size_t)s * C1 + c0);
#pragma unroll
        for (int q = 0; q < 4; q++) {
            float2 f = h2f2((&u.x)[q]);
            acc[2 * q]     += wgt * f.x;
            acc[2 * q + 1] += wgt * f.y;
        }
    }
    float inv = 1.f / sum;
    __half2 p0 = __floats2half2_rn(fmaxf(acc[0] * inv + bb[0], 0.f), fmaxf(acc[1] * inv + bb[1], 0.f));
    __half2 p1 = __floats2half2_rn(fmaxf(acc[2] * inv + bb[2], 0.f), fmaxf(acc[3] * inv + bb[3], 0.f));
    __half2 p2 = __floats2half2_rn(fmaxf(acc[4] * inv + bb[4], 0.f), fmaxf(acc[5] * inv + bb[5], 0.f));
    __half2 p3 = __floats2half2_rn(fmaxf(acc[6] * inv + bb[6], 0.f), fmaxf(acc[7] * inv + bb[7], 0.f));
    uint4 u;
    u.x = *reinterpret_cast<unsigned*>(&p0);
    u.y = *reinterpret_cast<unsigned*>(&p1);
    u.z = *reinterpret_cast<unsigned*>(&p2);
    u.w = *reinterpret_cast<unsigned*>(&p3);
    *(uint4*)outp = u;
}

// ---------------- layer-2 aggregation: warp per dst, SINGLE PASS -----------
__global__ void __launch_bounds__(256) k_agg2(const float* __restrict__ b2,
                                              float* __restrict__ out) {
    int wid = (blockIdx.x * blockDim.x + threadIdx.x) >> 5;
    int lane = threadIdx.x & 31;
    if (wid >= NN) return;
    int beg = g_offs[wid], end = g_offs[wid + 1];
    int c0 = lane * 2;
    float* outp = out + (size_t)wid * CIN + c0;
    float b0 = b2[c0], b1v = b2[c0 + 1];
    if (beg == end) {
        outp[0] = b0;
        outp[1] = b1v;
        return;
    }
    float ad = g_ad2[wid];
    float sum = 0.f;
    float acc0 = 0.f, acc1 = 0.f;
    int i = beg;
    for (; i + 4 <= end; i += 4) {
        int s0 = g_csrc[i], s1 = g_csrc[i + 1], s2 = g_csrc[i + 2], s3 = g_csrc[i + 3];
        float e0 = g_as2[s0], e1 = g_as2[s1], e2 = g_as2[s2], e3 = g_as2[s3];
        unsigned u0 = *(const unsigned*)(g_h2 + (size_t)s0 * CIN + c0);
        unsigned u1 = *(const unsigned*)(g_h2 + (size_t)s1 * CIN + c0);
        unsigned u2 = *(const unsigned*)(g_h2 + (size_t)s2 * CIN + c0);
        unsigned u3 = *(const unsigned*)(g_h2 + (size_t)s3 * CIN + c0);
        float w0 = __expf(lrelu(e0 + ad));
        float w1 = __expf(lrelu(e1 + ad));
        float w2 = __expf(lrelu(e2 + ad));
        float w3 = __expf(lrelu(e3 + ad));
        sum += (w0 + w1) + (w2 + w3);
        float2 v0 = h2f2(u0), v1 = h2f2(u1), v2 = h2f2(u2), v3 = h2f2(u3);
        acc0 += w0 * v0.x + w1 * v1.x + w2 * v2.x + w3 * v3.x;
        acc1 += w0 * v0.y + w1 * v1.y + w2 * v2.y + w3 * v3.y;
    }
    for (; i < end; i++) {
        int s = g_csrc[i];
        float wgt = __expf(lrelu(g_as2[s] + ad));
        sum += wgt;
        float2 v = h2f2(*(const unsigned*)(g_h2 + (size_t)s * CIN + c0));
        acc0 += wgt * v.x;
        acc1 += wgt * v.y;
    }
    float inv = 1.f / sum;
    outp[0] = acc0 * inv + b0;
    outp[1] = acc1 * inv + b1v;
}

// ---------------- launcher -------------------------------------------------
extern "C" void kernel_launch(void* const* d_in, const int* in_sizes, int n_in,
                              void* d_out, int out_size) {
    const float* x    = (const float*)d_in[0];
    const int*   ei   = (const int*)d_in[1];   // int32 (JAX x64 disabled)
    const float* W1   = (const float*)d_in[2];
    const float* as1  = (const float*)d_in[3];
    const float* ad1  = (const float*)d_in[4];
    const float* b1   = (const float*)d_in[5];
    const float* W2   = (const float*)d_in[6];
    const float* as2  = (const float*)d_in[7];
    const float* ad2  = (const float*)d_in[8];
    const float* b2   = (const float*)d_in[9];
    float* out = (float*)d_out;

    cudaStream_t side;
    cudaEvent_t ev_fork, ev_join;
    cudaStreamCreateWithFlags(&side, cudaStreamNonBlocking);
    cudaEventCreateWithFlags(&ev_fork, cudaEventDisableTiming);
    cudaEventCreateWithFlags(&ev_join, cudaEventDisableTiming);

    // fork: gemm1 on side stream (independent of CSR build)
    cudaEventRecord(ev_fork, 0);
    cudaStreamWaitEvent(side, ev_fork, 0);
    k_gemm1<<<(NN + 63) / 64, 256, 0, side>>>(x, W1, as1, ad1);
    cudaEventRecord(ev_join, side);

    // CSR build on default stream
    void* degp = nullptr;
    cudaGetSymbolAddress(&degp, g_deg);
    cudaMemsetAsync(degp, 0, NN * sizeof(int));
    k_count<<<(EE / 4 + 255) / 256, 256>>>(ei);
    k_scan1<<<(NN + 1023) / 1024, 1024>>>();
    k_scan2<<<1, 64>>>();
    k_scan3<<<(NN + 255) / 256, 256>>>();
    k_scatter<<<(EE / 4 + 255) / 256, 256>>>(ei);

    // join: agg1 needs both gemm1 and CSR
    cudaStreamWaitEvent(0, ev_join, 0);
    k_agg1<<<(NN + 7) / 8, 256>>>(b1);

    k_gemm2<<<(NN + 127) / 128, 256>>>(W2, as2, ad2);
    k_agg2<<<(NN + 7) / 8, 256>>>(b2, out);

    // host-side cleanup (no device ops)
    cudaEventDestroy(ev_fork);
    cudaEventDestroy(ev_join);
    cudaStreamDestroy(side);
}

// round 9
// speedup vs baseline: 2.0824x; 1.0061x over previous
#include <cuda_runtime.h>
#include <cuda_fp16.h>
#include <mma.h>

using namespace nvcuda;

#define NN 50000
#define NPAD 50048   // 128-row tiles for wmma gemm2
#define EE 800000
#define CIN 64
#define H1 4
#define C1 256   // H1*64
#define NEG 0.2f

// ---------------- device scratch (no runtime allocation allowed) -----------
__device__ __half g_h1b[NN * C1];    // layer1 linear output, fp16 (gather path)
__device__ __half g_h1r[NPAD * C1];  // relu(agg layer1), fp16; padded for wmma
__device__ float g_as1[NN * H1];
__device__ float g_ad1[NN * H1];
__device__ __half g_h2[NN * CIN];    // layer2 linear output, fp16 (gather path)
__device__ __half g_W2h[C1 * CIN];   // W2 converted to fp16
__device__ float g_as2[NN];
__device__ float g_ad2[NN];
__device__ int   g_deg[NN];
__device__ int   g_offs[NN + 1];
__device__ int   g_cur[NN];
__device__ int   g_csrc[EE];
__device__ int   g_part[64];

__device__ __forceinline__ int clampN(int v) {
    return v < 0 ? 0 : (v >= NN ? NN - 1 : v);
}

// ---------------- packed f32x2 helpers (Blackwell FFMA2) -------------------
__device__ __forceinline__ unsigned long long pk2(float x, float y) {
    unsigned long long r;
    asm("mov.b64 %0, {%1, %2};" : "=l"(r)
        : "r"(__float_as_uint(x)), "r"(__float_as_uint(y)));
    return r;
}
__device__ __forceinline__ void upk2(unsigned long long v, float &x, float &y) {
    unsigned int lo, hi;
    asm("mov.b64 {%0, %1}, %2;" : "=r"(lo), "=r"(hi) : "l"(v));
    x = __uint_as_float(lo); y = __uint_as_float(hi);
}
__device__ __forceinline__ void fma2(unsigned long long &d,
                                     unsigned long long a,
                                     unsigned long long b) {
    asm("fma.rn.f32x2 %0, %1, %2, %0;" : "+l"(d) : "l"(a), "l"(b));
}

__device__ __forceinline__ float2 h2f2(unsigned u) {
    return __half22float2(*reinterpret_cast<__half2*>(&u));
}

// ---------------- CSR construction ----------------------------------------
__global__ void k_count(const int* __restrict__ ei) {
    int e4 = blockIdx.x * blockDim.x + threadIdx.x;
    if (e4 < EE / 4) {
        int4 d = *(const int4*)(ei + EE + 4 * e4);
        atomicAdd(&g_deg[clampN(d.x)], 1);
        atomicAdd(&g_deg[clampN(d.y)], 1);
        atomicAdd(&g_deg[clampN(d.z)], 1);
        atomicAdd(&g_deg[clampN(d.w)], 1);
    }
}

__global__ void __launch_bounds__(1024) k_scan1() {
    __shared__ int wsum[32];
    int t = threadIdx.x, b = blockIdx.x;
    int i = b * 1024 + t;
    int lane = t & 31, w = t >> 5;
    int v = (i < NN) ? g_deg[i] : 0;
    int x = v;
#pragma unroll
    for (int off = 1; off < 32; off <<= 1) {
        int u = __shfl_up_sync(0xffffffffu, x, off);
        if (lane >= off) x += u;
    }
    if (lane == 31) wsum[w] = x;
    __syncthreads();
    if (w == 0) {
        int s = wsum[lane];
#pragma unroll
        for (int off = 1; off < 32; off <<= 1) {
            int u = __shfl_up_sync(0xffffffffu, s, off);
            if (lane >= off) s += u;
        }
        wsum[lane] = s;
    }
    __syncthreads();
    int incl = x + (w > 0 ? wsum[w - 1] : 0);
    if (i < NN) g_offs[i + 1] = incl;
    if (t == 1023) g_part[b] = incl;
}

__global__ void k_scan2() {
    __shared__ int sm[64];
    int t = threadIdx.x;
    sm[t] = (t < 49) ? g_part[t] : 0;
    __syncthreads();
#pragma unroll
    for (int off = 1; off < 64; off <<= 1) {
        int u = (t >= off) ? sm[t - off] : 0;
        __syncthreads();
        sm[t] += u;
        __syncthreads();
    }
    if (t < 49) g_part[t] = t ? sm[t - 1] : 0;
}

__global__ void k_scan3() {
    int i = blockIdx.x * blockDim.x + threadIdx.x;
    if (i == 0) g_offs[0] = 0;
    if (i < NN) {
        int v = g_offs[i + 1] + g_part[i >> 10];
        g_offs[i + 1] = v;
        g_cur[i] = v - g_deg[i];
    }
}

__global__ void k_scatter(const int* __restrict__ ei) {
    int e4 = blockIdx.x * blockDim.x + threadIdx.x;
    if (e4 < EE / 4) {
        int4 s = *(const int4*)(ei + 4 * e4);
        int4 d = *(const int4*)(ei + EE + 4 * e4);
        int p0 = atomicAdd(&g_cur[clampN(d.x)], 1);
        int p1 = atomicAdd(&g_cur[clampN(d.y)], 1);
        int p2 = atomicAdd(&g_cur[clampN(d.z)], 1);
        int p3 = atomicAdd(&g_cur[clampN(d.w)], 1);
        g_csrc[p0] = clampN(s.x);
        g_csrc[p1] = clampN(s.y);
        g_csrc[p2] = clampN(s.z);
        g_csrc[p3] = clampN(s.w);
    }
}

// ---------------- W2 -> fp16 convert (runs in fork, off critical path) -----
__global__ void k_convW2(const float* __restrict__ W2) {
    int i = blockIdx.x * blockDim.x + threadIdx.x;
    if (i < C1 * CIN) g_W2h[i] = __float2half(W2[i]);
}

// ---------------- GEMM 1: h1 = x[N,64] @ W1[64,256]  (FFMA2, fp32) ---------
__global__ void __launch_bounds__(256) k_gemm1(const float* __restrict__ x,
                                               const float* __restrict__ W1,
                                               const float* __restrict__ att_s,
                                               const float* __restrict__ att_d) {
    __shared__ float sx[64 * 32];
    __shared__ float sW[32 * 256];
    int t = threadIdx.x;
    int row0 = blockIdx.x * 64;
    int cg = t & 31, rg = t >> 5;
    unsigned long long acc[8][4];
#pragma unroll
    for (int m = 0; m < 8; m++)
#pragma unroll
        for (int c = 0; c < 4; c++) acc[m][c] = 0ull;

    for (int kc = 0; kc < 2; kc++) {
        __syncthreads();
        {
            float4* s4 = (float4*)sx;
#pragma unroll
            for (int q = 0; q < 2; q++) {
                int idx = t + q * 256;
                int row = idx >> 3, j = idx & 7;
                float4 v = make_float4(0.f, 0.f, 0.f, 0.f);
                if (row0 + row < NN)
                    v = *(const float4*)(x + (size_t)(row0 + row) * 64 + kc * 32 + j * 4);
                s4[idx] = v;
            }
            float4* w4 = (float4*)sW;
            const float4* wg = (const float4*)(W1 + kc * 32 * 256);
#pragma unroll
            for (int q = 0; q < 8; q++) w4[t + q * 256] = wg[t + q * 256];
        }
        __syncthreads();
        const float* xrow = sx + rg * 8 * 32;
#pragma unroll 2
        for (int k4 = 0; k4 < 8; k4++) {
            float4 xq[8];
#pragma unroll
            for (int m = 0; m < 8; m++)
                xq[m] = *(const float4*)(xrow + m * 32 + k4 * 4);
#pragma unroll
            for (int j = 0; j < 4; j++) {
                const ulonglong2* wp =
                    (const ulonglong2*)(sW + (k4 * 4 + j) * 256 + cg * 8);
                ulonglong2 wa = wp[0];
                ulonglong2 wb = wp[1];
#pragma unroll
                for (int m = 0; m < 8; m++) {
                    float xs = (j == 0) ? xq[m].x : (j == 1) ? xq[m].y
                             : (j == 2) ? xq[m].z : xq[m].w;
                    unsigned long long xd = pk2(xs, xs);
                    fma2(acc[m][0], xd, wa.x);
                    fma2(acc[m][1], xd, wa.y);
                    fma2(acc[m][2], xd, wb.x);
                    fma2(acc[m][3], xd, wb.y);
                }
            }
        }
    }
    int cb = cg * 8;
    float asv[8], adv[8];
#pragma unroll
    for (int q = 0; q < 8; q++) { asv[q] = att_s[cb + q]; adv[q] = att_d[cb + q]; }
#pragma unroll
    for (int m = 0; m < 8; m++) {
        int row = row0 + rg * 8 + m;
        float v[8];
        upk2(acc[m][0], v[0], v[1]);
        upk2(acc[m][1], v[2], v[3]);
        upk2(acc[m][2], v[4], v[5]);
        upk2(acc[m][3], v[6], v[7]);
        float ps = 0.f, pd = 0.f;
#pragma unroll
        for (int q = 0; q < 8; q++) { ps += v[q] * asv[q]; pd += v[q] * adv[q]; }
#pragma unroll
        for (int off = 4; off; off >>= 1) {
            ps += __shfl_xor_sync(0xffffffffu, ps, off);
            pd += __shfl_xor_sync(0xffffffffu, pd, off);
        }
        if (row < NN) {
            __half2 p0 = __floats2half2_rn(v[0], v[1]);
            __half2 p1 = __floats2half2_rn(v[2], v[3]);
            __half2 p2 = __floats2half2_rn(v[4], v[5]);
            __half2 p3 = __floats2half2_rn(v[6], v[7]);
            uint4 u;
            u.x = *reinterpret_cast<unsigned*>(&p0);
            u.y = *reinterpret_cast<unsigned*>(&p1);
            u.z = *reinterpret_cast<unsigned*>(&p2);
            u.w = *reinterpret_cast<unsigned*>(&p3);
            *(uint4*)(g_h1b + (size_t)row * C1 + cb) = u;
            if ((cg & 7) == 0) {
                int h = cg >> 3;
                g_as1[row * H1 + h] = ps;
                g_ad1[row * H1 + h] = pd;
            }
        }
    }
}

// ---------------- GEMM 2 (WMMA fp16 tensor cores): h2 = h1r @ W2h ----------
__global__ void __launch_bounds__(256) k_gemm2(const float* __restrict__ att_s,
                                               const float* __restrict__ att_d) {
    __shared__ float sc[8][16 * 64];    // 32KB
    int t = threadIdx.x, w = t >> 5, lane = t & 31;
    int row0 = blockIdx.x * 128 + w * 16;

    wmma::fragment<wmma::accumulator, 16, 16, 16, float> accf[4];
#pragma unroll
    for (int n = 0; n < 4; n++) wmma::fill_fragment(accf[n], 0.f);

    const __half* Abase = g_h1r + (size_t)row0 * C1;
#pragma unroll 4
    for (int k = 0; k < 16; k++) {
        wmma::fragment<wmma::matrix_a, 16, 16, 16, __half, wmma::row_major> af;
        wmma::load_matrix_sync(af, Abase + k * 16, C1);
#pragma unroll
        for (int n = 0; n < 4; n++) {
            wmma::fragment<wmma::matrix_b, 16, 16, 16, __half, wmma::row_major> bf;
            wmma::load_matrix_sync(bf, g_W2h + k * 16 * CIN + n * 16, CIN);
            wmma::mma_sync(accf[n], af, bf, accf[n]);
        }
    }
#pragma unroll
    for (int n = 0; n < 4; n++)
        wmma::store_matrix_sync(&sc[w][n * 16], accf[n], 64, wmma::mem_row_major);
    __syncwarp();

    // epilogue: 2 lanes per row; each handles 32 cols
    int r = lane >> 1, half = lane & 1;
    int cb = half * 32;
    const float* rowp = &sc[w][r * 64 + cb];
    float ps = 0.f, pd = 0.f;
    float vv[32];
#pragma unroll
    for (int q = 0; q < 32; q++) {
        vv[q] = rowp[q];
        ps += vv[q] * att_s[cb + q];
        pd += vv[q] * att_d[cb + q];
    }
    ps += __shfl_xor_sync(0xffffffffu, ps, 1);
    pd += __shfl_xor_sync(0xffffffffu, pd, 1);
    int row = row0 + r;
    if (row < NN) {
        // pack 32 floats -> 16 half2 -> FOUR uint4 stores (8 halves each)
        unsigned up[16];
#pragma unroll
        for (int q = 0; q < 16; q++) {
            __half2 h = __floats2half2_rn(vv[2 * q], vv[2 * q + 1]);
            up[q] = *reinterpret_cast<unsigned*>(&h);
        }
        __half* op = g_h2 + (size_t)row * CIN + cb;
        *(uint4*)(op + 0)  = make_uint4(up[0],  up[1],  up[2],  up[3]);
        *(uint4*)(op + 8)  = make_uint4(up[4],  up[5],  up[6],  up[7]);
        *(uint4*)(op + 16) = make_uint4(up[8],  up[9],  up[10], up[11]);
        *(uint4*)(op + 24) = make_uint4(up[12], up[13], up[14], up[15]);
        if (half == 0) { g_as2[row] = ps; g_ad2[row] = pd; }
    }
}

__device__ __forceinline__ float lrelu(float x) {
    return x > 0.f ? x : NEG * x;
}

// ---------------- layer-1 aggregation: warp per dst, single pass -----------
__global__ void __launch_bounds__(256) k_agg1(const float* __restrict__ b1) {
    int wid = (blockIdx.x * blockDim.x + threadIdx.x) >> 5;
    int lane = threadIdx.x & 31;
    if (wid >= NN) return;
    int beg = g_offs[wid], end = g_offs[wid + 1];
    int c0 = lane * 8;
    __half* outp = g_h1r + (size_t)wid * C1 + c0;
    float bb[8];
#pragma unroll
    for (int q = 0; q < 8; q++) bb[q] = b1[c0 + q];
    if (beg == end) {
        __half2 p0 = __floats2half2_rn(fmaxf(bb[0], 0.f), fmaxf(bb[1], 0.f));
        __half2 p1 = __floats2half2_rn(fmaxf(bb[2], 0.f), fmaxf(bb[3], 0.f));
        __half2 p2 = __floats2half2_rn(fmaxf(bb[4], 0.f), fmaxf(bb[5], 0.f));
        __half2 p3 = __floats2half2_rn(fmaxf(bb[6], 0.f), fmaxf(bb[7], 0.f));
        uint4 u;
        u.x = *reinterpret_cast<unsigned*>(&p0);
        u.y = *reinterpret_cast<unsigned*>(&p1);
        u.z = *reinterpret_cast<unsigned*>(&p2);
        u.w = *reinterpret_cast<unsigned*>(&p3);
        *(uint4*)outp = u;
        return;
    }
    int head = lane >> 3;
    float adh = g_ad1[wid * H1 + head];
    float sum = 0.f;
    float acc[8];
#pragma unroll
    for (int q = 0; q < 8; q++) acc[q] = 0.f;
    int i = beg;
    for (; i + 4 <= end; i += 4) {
        int s0 = g_csrc[i], s1 = g_csrc[i + 1], s2 = g_csrc[i + 2], s3 = g_csrc[i + 3];
        float A0 = g_as1[s0 * H1 + head];
        float A1 = g_as1[s1 * H1 + head];
        float A2 = g_as1[s2 * H1 + head];
        float A3 = g_as1[s3 * H1 + head];
        uint4 u0 = *(const uint4*)(g_h1b + (size_t)s0 * C1 + c0);
        uint4 u1 = *(const uint4*)(g_h1b + (size_t)s1 * C1 + c0);
        uint4 u2 = *(const uint4*)(g_h1b + (size_t)s2 * C1 + c0);
        uint4 u3 = *(const uint4*)(g_h1b + (size_t)s3 * C1 + c0);
        float w0 = __expf(lrelu(A0 + adh));
        float w1 = __expf(lrelu(A1 + adh));
        float w2 = __expf(lrelu(A2 + adh));
        float w3 = __expf(lrelu(A3 + adh));
        sum += (w0 + w1) + (w2 + w3);
#pragma unroll
        for (int q = 0; q < 4; q++) {
            float2 f0 = h2f2((&u0.x)[q]);
            float2 f1 = h2f2((&u1.x)[q]);
            float2 f2 = h2f2((&u2.x)[q]);
            float2 f3 = h2f2((&u3.x)[q]);
            acc[2 * q]     += w0 * f0.x + w1 * f1.x + w2 * f2.x + w3 * f3.x;
            acc[2 * q + 1] += w0 * f0.y + w1 * f1.y + w2 * f2.y + w3 * f3.y;
        }
    }
    for (; i < end; i++) {
        int s = g_csrc[i];
        float wgt = __expf(lrelu(g_as1[s * H1 + head] + adh));
        sum += wgt;
        uint4 u = *(const uint4*)(g_h1b + (size_t)s * C1 + c0);
#pragma unroll
        for (int q = 0; q < 4; q++) {
            float2 f = h2f2((&u.x)[q]);
            acc[2 * q]     += wgt * f.x;
            acc[2 * q + 1] += wgt * f.y;
        }
    }
    float inv = 1.f / sum;
    __half2 p0 = __floats2half2_rn(fmaxf(acc[0] * inv + bb[0], 0.f), fmaxf(acc[1] * inv + bb[1], 0.f));
    __half2 p1 = __floats2half2_rn(fmaxf(acc[2] * inv + bb[2], 0.f), fmaxf(acc[3] * inv + bb[3], 0.f));
    __half2 p2 = __floats2half2_rn(fmaxf(acc[4] * inv + bb[4], 0.f), fmaxf(acc[5] * inv + bb[5], 0.f));
    __half2 p3 = __floats2half2_rn(fmaxf(acc[6] * inv + bb[6], 0.f), fmaxf(acc[7] * inv + bb[7], 0.f));
    uint4 u;
    u.x = *reinterpret_cast<unsigned*>(&p0);
    u.y = *reinterpret_cast<unsigned*>(&p1);
    u.z = *reinterpret_cast<unsigned*>(&p2);
    u.w = *reinterpret_cast<unsigned*>(&p3);
    *(uint4*)outp = u;
}

// ---------------- layer-2 aggregation: warp per dst, single pass -----------
__global__ void __launch_bounds__(256) k_agg2(const float* __restrict__ b2,
                                              float* __restrict__ out) {
    int wid = (blockIdx.x * blockDim.x + threadIdx.x) >> 5;
    int lane = threadIdx.x & 31;
    if (wid >= NN) return;
    int beg = g_offs[wid], end = g_offs[wid + 1];
    int c0 = lane * 2;
    float* outp = out + (size_t)wid * CIN + c0;
    float b0 = b2[c0], b1v = b2[c0 + 1];
    if (beg == end) {
        outp[0] = b0;
        outp[1] = b1v;
        return;
    }
    float ad = g_ad2[wid];
    float sum = 0.f;
    float acc0 = 0.f, acc1 = 0.f;
    int i = beg;
    for (; i + 4 <= end; i += 4) {
        int s0 = g_csrc[i], s1 = g_csrc[i + 1], s2 = g_csrc[i + 2], s3 = g_csrc[i + 3];
        float e0 = g_as2[s0], e1 = g_as2[s1], e2 = g_as2[s2], e3 = g_as2[s3];
        unsigned u0 = *(const unsigned*)(g_h2 + (size_t)s0 * CIN + c0);
        unsigned u1 = *(const unsigned*)(g_h2 + (size_t)s1 * CIN + c0);
        unsigned u2 = *(const unsigned*)(g_h2 + (size_t)s2 * CIN + c0);
        unsigned u3 = *(const unsigned*)(g_h2 + (size_t)s3 * CIN + c0);
        float w0 = __expf(lrelu(e0 + ad));
        float w1 = __expf(lrelu(e1 + ad));
        float w2 = __expf(lrelu(e2 + ad));
        float w3 = __expf(lrelu(e3 + ad));
        sum += (w0 + w1) + (w2 + w3);
        float2 v0 = h2f2(u0), v1 = h2f2(u1), v2 = h2f2(u2), v3 = h2f2(u3);
        acc0 += w0 * v0.x + w1 * v1.x + w2 * v2.x + w3 * v3.x;
        acc1 += w0 * v0.y + w1 * v1.y + w2 * v2.y + w3 * v3.y;
    }
    for (; i < end; i++) {
        int s = g_csrc[i];
        float wgt = __expf(lrelu(g_as2[s] + ad));
        sum += wgt;
        float2 v = h2f2(*(const unsigned*)(g_h2 + (size_t)s * CIN + c0));
        acc0 += wgt * v.x;
        acc1 += wgt * v.y;
    }
    float inv = 1.f / sum;
    outp[0] = acc0 * inv + b0;
    outp[1] = acc1 * inv + b1v;
}

// ---------------- launcher -------------------------------------------------
extern "C" void kernel_launch(void* const* d_in, const int* in_sizes, int n_in,
                              void* d_out, int out_size) {
    const float* x    = (const float*)d_in[0];
    const int*   ei   = (const int*)d_in[1];
    const float* W1   = (const float*)d_in[2];
    const float* as1  = (const float*)d_in[3];
    const float* ad1  = (const float*)d_in[4];
    const float* b1   = (const float*)d_in[5];
    const float* W2   = (const float*)d_in[6];
    const float* as2  = (const float*)d_in[7];
    const float* ad2  = (const float*)d_in[8];
    const float* b2   = (const float*)d_in[9];
    float* out = (float*)d_out;

    cudaStream_t side;
    cudaEvent_t ev_fork, ev_join;
    cudaStreamCreateWithFlags(&side, cudaStreamNonBlocking);
    cudaEventCreateWithFlags(&ev_fork, cudaEventDisableTiming);
    cudaEventCreateWithFlags(&ev_join, cudaEventDisableTiming);

    // fork: W2 convert + gemm1 on side stream (independent of CSR build)
    cudaEventRecord(ev_fork, 0);
    cudaStreamWaitEvent(side, ev_fork, 0);
    k_convW2<<<(C1 * CIN + 255) / 256, 256, 0, side>>>(W2);
    k_gemm1<<<(NN + 63) / 64, 256, 0, side>>>(x, W1, as1, ad1);
    cudaEventRecord(ev_join, side);

    // CSR build on default stream
    void* degp = nullptr;
    cudaGetSymbolAddress(&degp, g_deg);
    cudaMemsetAsync(degp, 0, NN * sizeof(int));
    k_count<<<(EE / 4 + 255) / 256, 256>>>(ei);
    k_scan1<<<(NN + 1023) / 1024, 1024>>>();
    k_scan2<<<1, 64>>>();
    k_scan3<<<(NN + 255) / 256, 256>>>();
    k_scatter<<<(EE / 4 + 255) / 256, 256>>>(ei);

    // join: agg1 needs both gemm1 and CSR
    cudaStreamWaitEvent(0, ev_join, 0);
    k_agg1<<<(NN + 7) / 8, 256>>>(b1);

    k_gemm2<<<(NPAD + 127) / 128, 256>>>(as2, ad2);
    k_agg2<<<(NN + 7) / 8, 256>>>(b2, out);

    cudaEventDestroy(ev_fork);
    cudaEventDestroy(ev_join);
    cudaStreamDestroy(side);
}